// round 13
// baseline (speedup 1.0000x reference)
#include <cuda_runtime.h>
#include <cuda_fp16.h>
#include <cstdint>

// ---------------- problem dims ----------------
#define BB 256
#define TT 512
#define II 512
#define HH 1024
#define OO 256

// ---------------- static device scratch (allocation-free) ----------------
__device__ __align__(16) float g_pre[BB * TT * HH];
__device__ __align__(16) __half g_xf[BB * TT * II];          // x as fp16
__device__ __align__(16) __half g_h1f[BB * TT * HH];         // hidden seq fp16 (both layers)
__device__ __align__(16) float g_h2f[BB * HH];               // layer1 final fp32
__device__ __align__(16) __half g_wih0[HH * II];
__device__ __align__(16) __half g_wih1[HH * HH];
__device__ __align__(16) __half g_whh0[HH * HH];
__device__ __align__(16) __half g_whh1[HH * HH];
__device__ __align__(16) float g_bias0[HH];
__device__ __align__(16) float g_bias1[HH];
// dataflow flags: 8 groups x 32 n-tiles, padded to 32B each
__device__ unsigned g_flags[8 * 32 * 8];

// ---------------- PTX helpers (baseline PTX only) ----------------
__device__ __forceinline__ uint32_t smem_u32(const void* p) {
    uint32_t a;
    asm("{ .reg .u64 t; cvta.to.shared.u64 t, %1; cvt.u32.u64 %0, t; }" : "=r"(a) : "l"(p));
    return a;
}
#define CP16(dst, src) \
    asm volatile("cp.async.cg.shared.global [%0], [%1], 16;" :: "r"(dst), "l"(src) : "memory")
#define CP_COMMIT() asm volatile("cp.async.commit_group;" ::: "memory")
#define CP_WAIT(n)  asm volatile("cp.async.wait_group %0;" :: "n"(n) : "memory")

#define LDMX4(r, addr) \
    asm volatile("ldmatrix.sync.aligned.m8n8.x4.shared.b16 {%0,%1,%2,%3}, [%4];" \
                 : "=r"((r)[0]), "=r"((r)[1]), "=r"((r)[2]), "=r"((r)[3]) : "r"(addr))

#define MMAH16816(d, a, b0, b1) \
    asm volatile("mma.sync.aligned.m16n8k16.row.col.f32.f16.f16.f32 " \
                 "{%0,%1,%2,%3},{%4,%5,%6,%7},{%8,%9},{%0,%1,%2,%3};" \
                 : "+f"((d)[0]), "+f"((d)[1]), "+f"((d)[2]), "+f"((d)[3]) \
                 : "r"((a)[0]), "r"((a)[1]), "r"((a)[2]), "r"((a)[3]), "r"(b0), "r"(b1))

__device__ __forceinline__ unsigned ld_acq(const unsigned* p) {
    unsigned v;
    asm volatile("ld.acquire.gpu.u32 %0, [%1];" : "=r"(v) : "l"(p) : "memory");
    return v;
}
__device__ __forceinline__ void st_rel(unsigned* p, unsigned v) {
    asm volatile("st.release.gpu.u32 [%0], %1;" :: "l"(p), "r"(v) : "memory");
}

// ---------------- prep kernels ----------------
__global__ void to_f16v(const float4* __restrict__ s, uint2* __restrict__ o, long long n4) {
    long long i = (long long)blockIdx.x * blockDim.x + threadIdx.x;
    if (i < n4) {
        float4 v = s[i];
        __half2 a = __floats2half2_rn(v.x, v.y);
        __half2 b = __floats2half2_rn(v.z, v.w);
        uint2 r;
        r.x = *(uint32_t*)&a; r.y = *(uint32_t*)&b;
        o[i] = r;
    }
}
__global__ void bias_combine(const float* __restrict__ a, const float* __restrict__ b,
                             float* __restrict__ out, int n) {
    int i = blockIdx.x * blockDim.x + threadIdx.x;
    if (i < n) out[i] = a[i] + b[i];
}
__global__ void clear_flags(unsigned* f, int n) {
    int i = blockIdx.x * blockDim.x + threadIdx.x;
    if (i < n) f[i] = 0;
}

// ================= fp16 HMMA pre-activation GEMM (1-pass, 3-stage) =================
#define PG_STAGE 32768
#define PG_SMEM  (3 * PG_STAGE)

__global__ void __launch_bounds__(256, 1)
gemm_mma(const __half* __restrict__ Af, const __half* __restrict__ Wf,
         const float* __restrict__ bias, float* __restrict__ C, int K) {
    extern __shared__ __align__(128) char smem[];
    const uint32_t sb = smem_u32(smem);
    const int tid = threadIdx.x, l = tid & 31, w = tid >> 5;
    const long long m0 = (long long)blockIdx.x * 128;
    const int n0 = blockIdx.y * 128;
    const int nch = K >> 6;

    const int r0 = tid >> 3, c = tid & 7;
    const uint32_t sd0 = (uint32_t)r0 * 128 + (((uint32_t)c * 16) ^ (((uint32_t)r0 & 7) * 16));

    const int m_off = (w & 3) * 32, n_off = (w >> 2) * 64;
    const int arw = m_off + (l & 7) + ((l & 8) ? 8 : 0);
    const uint32_t abase = (uint32_t)arw * 128;
    const uint32_t ax = ((uint32_t)arw & 7) * 16;
    const uint32_t akb = (l & 16) ? 16 : 0;
    const int brw = n_off + (l & 7) + ((l & 16) ? 8 : 0);
    const uint32_t bbase = (uint32_t)brw * 128;
    const uint32_t bx = ((uint32_t)brw & 7) * 16;
    const uint32_t bkb = (l & 8) ? 16 : 0;

    float acc[2][8][4];
#pragma unroll
    for (int i = 0; i < 2; i++)
#pragma unroll
        for (int j = 0; j < 8; j++)
#pragma unroll
            for (int k = 0; k < 4; k++) acc[i][j][k] = 0.0f;

    auto issue = [&](int kc) {
        const uint32_t d = sb + (uint32_t)(kc % 3) * PG_STAGE;
        const int ko = kc * 64 + c * 8;
#pragma unroll
        for (int j = 0; j < 4; ++j) {
            const long long ar = (m0 + r0 + 32 * j) * (long long)K + ko;
            const long long wr = ((long long)(n0 + r0 + 32 * j)) * K + ko;
            const uint32_t du = d + sd0 + j * 4096;
            CP16(du,          Af + ar);
            CP16(du + 16384,  Wf + wr);
        }
        CP_COMMIT();
    };

    issue(0);
    issue(1);

    for (int kc = 0; kc < nch; ++kc) {
        if (kc < nch - 1) CP_WAIT(1); else CP_WAIT(0);
        __syncthreads();
        if (kc + 2 < nch) issue(kc + 2);

        const uint32_t st = sb + (uint32_t)(kc % 3) * PG_STAGE;
#pragma unroll
        for (int ks = 0; ks < 4; ++ks) {
            uint32_t ah0[4], ah1[4];
            const uint32_t ao = ((uint32_t)(ks * 32) + akb) ^ ax;
            LDMX4(ah0, st + abase + ao);
            LDMX4(ah1, st + abase + 2048 + ao);
            uint32_t bh[4][4];
            const uint32_t bo = ((uint32_t)(ks * 32) + bkb) ^ bx;
#pragma unroll
            for (int nb = 0; nb < 4; ++nb)
                LDMX4(bh[nb], st + 16384 + bbase + nb * 2048 + bo);
#pragma unroll
            for (int nb = 0; nb < 4; ++nb) {
                MMAH16816(acc[0][2 * nb],     ah0, bh[nb][0], bh[nb][1]);
                MMAH16816(acc[0][2 * nb + 1], ah0, bh[nb][2], bh[nb][3]);
                MMAH16816(acc[1][2 * nb],     ah1, bh[nb][0], bh[nb][1]);
                MMAH16816(acc[1][2 * nb + 1], ah1, bh[nb][2], bh[nb][3]);
            }
        }
        __syncthreads();
    }

#pragma unroll
    for (int mf = 0; mf < 2; ++mf) {
        const long long R0 = m0 + m_off + mf * 16 + (l >> 2);
#pragma unroll
        for (int nf = 0; nf < 8; ++nf) {
            const int col = n0 + n_off + nf * 8 + (l & 3) * 2;
            const float2 bv = __ldg((const float2*)(bias + col));
            float2 o0, o1;
            o0.x = acc[mf][nf][0] + bv.x; o0.y = acc[mf][nf][1] + bv.y;
            o1.x = acc[mf][nf][2] + bv.x; o1.y = acc[mf][nf][3] + bv.y;
            __stcg((float2*)(C + R0 * HH + col), o0);
            __stcg((float2*)(C + (R0 + 8) * HH + col), o1);
        }
    }
}

// ================= fp16 HMMA persistent recurrence (dataflow flags, 2 CTAs/SM) =================
// grid 256 = 8 batch-groups(32 rows) x 32 H-tiles(32 cols). 256 threads.
// 8 warps = 8 K-slots, warp tile 32m x 32n. W fp16 resident (64KB).
// h stored as full sequence; per-tile release flags replace the grid barrier:
// producers publish flag[g][ntile]=t+1 after writing h[t]; consumers acquire-poll
// only the 4 tiles covering each 128-K cp.async chunk. No global barrier.
#define RA_ST 65536              // stages AND reduce area both live here
#define RA_STG 8192              // per stage: 2 x 4KB 64-K sub-blocks
#define RN_SMEM (RA_ST + 32768)  // 96KB total

__global__ void __launch_bounds__(256, 2)
rnn_mma(const __half* __restrict__ Wf,
        const float* __restrict__ pre,
        __half* __restrict__ hseq,        // [B][T][H] fp16 sequence
        float* __restrict__ hfin) {       // optional final fp32 (layer 1)
    extern __shared__ __align__(128) char smem[];
    const uint32_t sb = smem_u32(smem);
    const int tid = threadIdx.x, l = tid & 31, w = tid >> 5;
    const int grp = blockIdx.x & 7;
    const int ntile = blockIdx.x >> 3;
    const int m0 = grp * 32;
    const int n0 = ntile * 32;
    unsigned* myflag = &g_flags[(grp * 32 + ntile) * 8];

    // resident W: 16 blocks of [32 rows][128B], swizzled (4KB each)
    for (int u = tid; u < 4096; u += 256) {
        const int kc = u >> 8, rem = u & 255, r = rem >> 3, cc = rem & 7;
        const uint32_t dst = (uint32_t)kc * 4096 + (uint32_t)r * 128 +
                             (((uint32_t)cc * 16) ^ (((uint32_t)r & 7) * 16));
        const long long src = (long long)(n0 + r) * HH + kc * 64 + cc * 8;
        *(uint4*)(smem + dst) = *(const uint4*)(Wf + src);
    }
    __syncthreads();

    // staging: per 128-K chunk, each thread stages 2 x 16B: row tid>>3, 16B-col tid&7
    const int srr = tid >> 3, scc = tid & 7;
    const uint32_t st0 = (uint32_t)srr * 128 + (((uint32_t)scc * 16) ^ (((uint32_t)srr & 7) * 16));

    // compute mapping: warp = kslot 0..7, tile 32m x 32n
    const int kslot = w;
    const int bsel = kslot >> 2;
    const int si = kslot & 3;
    const uint32_t ax = ((uint32_t)l & 7) * 16;
    const uint32_t akb = (l & 16) ? 16u : 0u;
    const uint32_t a0base = (uint32_t)(l & 15) * 128;
    const uint32_t bkb = (l & 8) ? 16u : 0u;
    const uint32_t b0base = (uint32_t)((l & 7) + ((l & 16) ? 8 : 0)) * 128;
    const uint32_t kob = (uint32_t)(si * 32);
    const uint32_t ao = (kob + akb) ^ ax;
    const uint32_t bo = (kob + bkb) ^ ax;

    // reduce/epilogue mapping: tid = rl*8 + rfg
    const int rl = tid >> 3;
    const int rfg = tid & 7;
    const int erow = m0 + (rfg >> 2) * 16 + (rl >> 2);
    const int ecol = n0 + (rfg & 3) * 8 + (rl & 3) * 2;
    const uint32_t rsw = ((uint32_t)rfg * 16) ^ (((uint32_t)rl & 7) * 16);

    for (int t = 0; t < TT; ++t) {
        // prefetch pre_t (independent of h)
        float2 p0 = __ldcg((const float2*)(pre + ((long long)erow * TT + t) * HH + ecol));
        float2 p1 = __ldcg((const float2*)(pre + ((long long)(erow + 8) * TT + t) * HH + ecol));

        float acc[2][4][4];
#pragma unroll
        for (int i = 0; i < 2; i++)
#pragma unroll
            for (int j = 0; j < 4; j++)
#pragma unroll
                for (int k = 0; k < 4; k++) acc[i][j][k] = 0.0f;

        if (t > 0) {
            const long long ab = ((long long)(m0 + srr) * TT + (t - 1)) * HH + scc * 8;

            auto issueA = [&](int cix) {
                const uint32_t d = sb + RA_ST + (uint32_t)(cix % 3) * RA_STG;
                CP16(d + st0,        hseq + ab + cix * 128);
                CP16(d + 4096 + st0, hseq + ab + cix * 128 + 64);
                CP_COMMIT();
            };

            // wait for tiles 0..7 (chunks 0,1), then prime pipeline
            if (tid < 8) {
                const unsigned* fp = &g_flags[(grp * 32 + tid) * 8];
                while (ld_acq(fp) < (unsigned)t) { }
            }
            __syncthreads();
            issueA(0);
            issueA(1);

            for (int cix = 0; cix < 8; ++cix) {
                if (cix < 7) CP_WAIT(1); else CP_WAIT(0);
                // wait for the 4 producer tiles of chunk cix+2
                if (cix + 2 < 8 && tid < 4) {
                    const unsigned* fp = &g_flags[(grp * 32 + 4 * (cix + 2) + tid) * 8];
                    while (ld_acq(fp) < (unsigned)t) { }
                }
                __syncthreads();
                if (cix + 2 < 8) issueA(cix + 2);

                const uint32_t stg = sb + RA_ST + (uint32_t)(cix % 3) * RA_STG;
                const uint32_t ahbuf = stg + (uint32_t)bsel * 4096;
                const uint32_t bhbuf = sb + (uint32_t)(2 * cix + bsel) * 4096;

                uint32_t ah0[4], ah1[4];
                LDMX4(ah0, ahbuf + a0base + ao);
                LDMX4(ah1, ahbuf + a0base + 2048 + ao);
                uint32_t bh0[4], bh1[4];
                LDMX4(bh0, bhbuf + b0base + bo);
                LDMX4(bh1, bhbuf + b0base + 2048 + bo);
                MMAH16816(acc[0][0], ah0, bh0[0], bh0[1]); MMAH16816(acc[0][1], ah0, bh0[2], bh0[3]);
                MMAH16816(acc[0][2], ah0, bh1[0], bh1[1]); MMAH16816(acc[0][3], ah0, bh1[2], bh1[3]);
                MMAH16816(acc[1][0], ah1, bh0[0], bh0[1]); MMAH16816(acc[1][1], ah1, bh0[2], bh0[3]);
                MMAH16816(acc[1][2], ah1, bh1[0], bh1[1]); MMAH16816(acc[1][3], ah1, bh1[2], bh1[3]);
            }
        }

        // ---- 8-way K reduction through smem (XOR-swizzled, conflict-free) ----
        __syncthreads();
        {
            char* wp = smem + RA_ST + kslot * 4096 + l * 128;
            const uint32_t wsw = ((uint32_t)l & 7) * 16;
#pragma unroll
            for (int mf = 0; mf < 2; ++mf)
#pragma unroll
                for (int nf = 0; nf < 4; ++nf)
                    *(float4*)(wp + (((uint32_t)(mf * 4 + nf) * 16) ^ wsw)) = *(float4*)acc[mf][nf];
        }
        __syncthreads();
        float s[4];
        s[0] = s[1] = s[2] = s[3] = 0.0f;
#pragma unroll
        for (int k = 0; k < 8; ++k) {
            const float4 u = *(const float4*)(smem + RA_ST + k * 4096 + rl * 128 + rsw);
            s[0] += u.x; s[1] += u.y; s[2] += u.z; s[3] += u.w;
        }

        // ---- epilogue: h = relu(sum + pre_t); store fp16 (+ final fp32) ----
        {
            const long long R0 = erow, R1 = erow + 8;
            float v0 = fmaxf(s[0] + p0.x, 0.0f);
            float v1 = fmaxf(s[1] + p0.y, 0.0f);
            float v2 = fmaxf(s[2] + p1.x, 0.0f);
            float v3 = fmaxf(s[3] + p1.y, 0.0f);
            __half2 ha = __floats2half2_rn(v0, v1);
            __half2 hb = __floats2half2_rn(v2, v3);
            const long long ob0 = (R0 * TT + t) * HH + ecol;
            const long long ob1 = (R1 * TT + t) * HH + ecol;
            __stcg((uint32_t*)(hseq + ob0), *(uint32_t*)&ha);
            __stcg((uint32_t*)(hseq + ob1), *(uint32_t*)&hb);
            if (hfin != nullptr && t == TT - 1) {
                __stcg((float2*)(hfin + R0 * HH + ecol), make_float2(v0, v1));
                __stcg((float2*)(hfin + R1 * HH + ecol), make_float2(v2, v3));
            }
        }

        // ---- publish: release our tile for step t ----
        __threadfence();
        __syncthreads();
        if (tid == 0) st_rel(myflag, (unsigned)(t + 1));
    }
}

// ---------------- small scalar GEMM for fc ----------------
template <int BM, int BN, int TM, int TN>
__global__ void __launch_bounds__((BM / TM) * (BN / TN))
gemm_nt(const float* __restrict__ A, long long a_stride,
        const float* __restrict__ W, const float* __restrict__ bias,
        float* __restrict__ C, long long c_stride, int K) {
    constexpr int BK = 16, TX = BN / TN, TY = BM / TM, NT = TX * TY;
    __shared__ __align__(16) float As[BK][BM];
    __shared__ __align__(16) float Ws[BK][BN];
    const int tid = threadIdx.x, tx = tid % TX, ty = tid / TX;
    const long long m0 = (long long)blockIdx.x * BM;
    const int n0 = blockIdx.y * BN;
    float acc[TM][TN];
#pragma unroll
    for (int i = 0; i < TM; i++)
#pragma unroll
        for (int j = 0; j < TN; j++) acc[i][j] = 0.0f;
    for (int kt = 0; kt < K; kt += BK) {
#pragma unroll
        for (int idx = tid; idx < BM * 4; idx += NT) {
            const int row = idx >> 2, kq = (idx & 3) * 4;
            const float4 v = *(const float4*)(A + (m0 + row) * a_stride + kt + kq);
            As[kq][row] = v.x; As[kq + 1][row] = v.y; As[kq + 2][row] = v.z; As[kq + 3][row] = v.w;
        }
#pragma unroll
        for (int idx = tid; idx < BN * 4; idx += NT) {
            const int row = idx >> 2, kq = (idx & 3) * 4;
            const float4 v = *(const float4*)(W + (long long)(n0 + row) * K + kt + kq);
            Ws[kq][row] = v.x; Ws[kq + 1][row] = v.y; Ws[kq + 2][row] = v.z; Ws[kq + 3][row] = v.w;
        }
        __syncthreads();
#pragma unroll
        for (int kk = 0; kk < BK; kk++) {
            float a[TM], b[TN];
#pragma unroll
            for (int i = 0; i < TM; i += 4) {
                const float4 v = *(const float4*)&As[kk][ty * TM + i];
                a[i] = v.x; a[i + 1] = v.y; a[i + 2] = v.z; a[i + 3] = v.w;
            }
#pragma unroll
            for (int j = 0; j < TN; j += 4) {
                const float4 v = *(const float4*)&Ws[kk][tx * TN + j];
                b[j] = v.x; b[j + 1] = v.y; b[j + 2] = v.z; b[j + 3] = v.w;
            }
#pragma unroll
            for (int i = 0; i < TM; i++)
#pragma unroll
                for (int j = 0; j < TN; j++) acc[i][j] = fmaf(a[i], b[j], acc[i][j]);
        }
        __syncthreads();
    }
#pragma unroll
    for (int i = 0; i < TM; i++) {
        const long long m = m0 + ty * TM + i;
#pragma unroll
        for (int j = 0; j < TN; j++)
            C[m * c_stride + n0 + tx * TN + j] = acc[i][j] + bias[n0 + tx * TN + j];
    }
}

// ---------------- launch ----------------
extern "C" void kernel_launch(void* const* d_in, const int* in_sizes, int n_in,
                              void* d_out, int out_size) {
    const float* x     = (const float*)d_in[0];
    const float* W_ih0 = (const float*)d_in[1];
    const float* W_hh0 = (const float*)d_in[2];
    const float* b_ih0 = (const float*)d_in[3];
    const float* b_hh0 = (const float*)d_in[4];
    const float* W_ih1 = (const float*)d_in[5];
    const float* W_hh1 = (const float*)d_in[6];
    const float* b_ih1 = (const float*)d_in[7];
    const float* b_hh1 = (const float*)d_in[8];
    const float* fc_w  = (const float*)d_in[9];
    const float* fc_b  = (const float*)d_in[10];
    float* out = (float*)d_out;

    float *p_pre, *p_b0, *p_b1, *p_h2f;
    __half *p_xf, *p_h1f;
    __half *p_wih0, *p_wih1, *p_whh0, *p_whh1;
    unsigned* p_flags;
    cudaGetSymbolAddress((void**)&p_pre, g_pre);
    cudaGetSymbolAddress((void**)&p_b0, g_bias0);
    cudaGetSymbolAddress((void**)&p_b1, g_bias1);
    cudaGetSymbolAddress((void**)&p_h2f, g_h2f);
    cudaGetSymbolAddress((void**)&p_xf, g_xf);
    cudaGetSymbolAddress((void**)&p_h1f, g_h1f);
    cudaGetSymbolAddress((void**)&p_wih0, g_wih0);
    cudaGetSymbolAddress((void**)&p_wih1, g_wih1);
    cudaGetSymbolAddress((void**)&p_whh0, g_whh0);
    cudaGetSymbolAddress((void**)&p_whh1, g_whh1);
    cudaGetSymbolAddress((void**)&p_flags, g_flags);

    cudaFuncSetAttribute(gemm_mma, cudaFuncAttributeMaxDynamicSharedMemorySize, PG_SMEM);
    cudaFuncSetAttribute(rnn_mma, cudaFuncAttributeMaxDynamicSharedMemorySize, RN_SMEM);

    const long long nx4 = (long long)BB * TT * II / 4;
    const long long nw04 = (long long)HH * II / 4;
    const long long nw4 = (long long)HH * HH / 4;
    const int nflags = 8 * 32 * 8;

    // 1: x -> fp16
    to_f16v<<<(unsigned)((nx4 + 255) / 256), 256>>>((const float4*)x, (uint2*)p_xf, nx4);
    // 2: W_ih0 -> fp16
    to_f16v<<<(unsigned)((nw04 + 255) / 256), 256>>>((const float4*)W_ih0, (uint2*)p_wih0, nw04);
    // 3: bias0
    bias_combine<<<(HH + 255) / 256, 256>>>(b_ih0, b_hh0, p_b0, HH);
    // 4: W_hh0 -> fp16
    to_f16v<<<(unsigned)((nw4 + 255) / 256), 256>>>((const float4*)W_hh0, (uint2*)p_whh0, nw4);
    // 5: pre0 = x @ W_ih0^T + bias0
    gemm_mma<<<dim3((BB * TT) / 128, HH / 128), 256, PG_SMEM>>>(
        p_xf, p_wih0, p_b0, p_pre, II);
    // 6: clear flags, layer-0 recurrence (dataflow)
    clear_flags<<<(nflags + 255) / 256, 256>>>(p_flags, nflags);
    rnn_mma<<<256, 256, RN_SMEM>>>(p_whh0, p_pre, p_h1f, nullptr);
    // 7: W_ih1 -> fp16
    to_f16v<<<(unsigned)((nw4 + 255) / 256), 256>>>((const float4*)W_ih1, (uint2*)p_wih1, nw4);
    // 8: bias1
    bias_combine<<<(HH + 255) / 256, 256>>>(b_ih1, b_hh1, p_b1, HH);
    // 9: pre1 = h1 @ W_ih1^T + bias1
    gemm_mma<<<dim3((BB * TT) / 128, HH / 128), 256, PG_SMEM>>>(
        p_h1f, p_wih1, p_b1, p_pre, HH);
    // 10: W_hh1 -> fp16
    to_f16v<<<(unsigned)((nw4 + 255) / 256), 256>>>((const float4*)W_hh1, (uint2*)p_whh1, nw4);
    // 11: clear flags, layer-1 recurrence (reuses g_h1f as its sequence buffer)
    clear_flags<<<(nflags + 255) / 256, 256>>>(p_flags, nflags);
    rnn_mma<<<256, 256, RN_SMEM>>>(p_whh1, p_pre, p_h1f, p_h2f);
    // 12: fc
    gemm_nt<32, 64, 4, 4><<<dim3(BB / 32, OO / 64), 128>>>(
        p_h2f, HH, fc_w, fc_b, out, OO, HH);
}

// round 14
// speedup vs baseline: 1.2348x; 1.2348x over previous
#include <cuda_runtime.h>
#include <cuda_fp16.h>
#include <cstdint>

// ---------------- problem dims ----------------
#define BB 256
#define TT 512
#define II 512
#define HH 1024
#define OO 256

// ---------------- static device scratch (allocation-free) ----------------
__device__ __align__(16) float g_pre[BB * TT * HH];          // pre0 (layer-0 addend)
__device__ __align__(16) float g_pre2[BB * TT * HH];         // pre1 (produced by fused kernel)
__device__ __align__(16) __half g_xf[BB * TT * II];
__device__ __align__(16) __half g_h1f[BB * TT * HH];         // layer0 hidden seq fp16
__device__ __align__(16) __half g_h2f16[2 * BB * HH];        // layer1 ping-pong fp16
__device__ __align__(16) float g_h2f[BB * HH];               // layer1 final fp32
__device__ __align__(16) __half g_wih0[HH * II];
__device__ __align__(16) __half g_wih1[HH * HH];
__device__ __align__(16) __half g_whh0[HH * HH];
__device__ __align__(16) __half g_whh1[HH * HH];
__device__ __align__(16) float g_bias0[HH];
__device__ __align__(16) float g_bias1[HH];
// per-group barrier state: group g uses slot g*32 (128B apart)
__device__ unsigned g_cnt2[256];
__device__ unsigned g_gen2[256];

// ---------------- PTX helpers (baseline PTX only) ----------------
__device__ __forceinline__ uint32_t smem_u32(const void* p) {
    uint32_t a;
    asm("{ .reg .u64 t; cvta.to.shared.u64 t, %1; cvt.u32.u64 %0, t; }" : "=r"(a) : "l"(p));
    return a;
}
#define CP16(dst, src) \
    asm volatile("cp.async.cg.shared.global [%0], [%1], 16;" :: "r"(dst), "l"(src) : "memory")
#define CP_COMMIT() asm volatile("cp.async.commit_group;" ::: "memory")
#define CP_WAIT(n)  asm volatile("cp.async.wait_group %0;" :: "n"(n) : "memory")

#define LDMX4(r, addr) \
    asm volatile("ldmatrix.sync.aligned.m8n8.x4.shared.b16 {%0,%1,%2,%3}, [%4];" \
                 : "=r"((r)[0]), "=r"((r)[1]), "=r"((r)[2]), "=r"((r)[3]) : "r"(addr))

#define MMAH16816(d, a, b0, b1) \
    asm volatile("mma.sync.aligned.m16n8k16.row.col.f32.f16.f16.f32 " \
                 "{%0,%1,%2,%3},{%4,%5,%6,%7},{%8,%9},{%0,%1,%2,%3};" \
                 : "+f"((d)[0]), "+f"((d)[1]), "+f"((d)[2]), "+f"((d)[3]) \
                 : "r"((a)[0]), "r"((a)[1]), "r"((a)[2]), "r"((a)[3]), "r"(b0), "r"(b1))

// ---------------- group grid barrier (32 CTAs per group) ----------------
__device__ __forceinline__ void grid_bar_g(int g) {
    __threadfence();
    __syncthreads();
    if (threadIdx.x == 0) {
        volatile unsigned* gen = (volatile unsigned*)&g_gen2[g * 32];
        unsigned my = *gen;
        if (atomicAdd(&g_cnt2[g * 32], 1u) == 31u) {
            atomicExch(&g_cnt2[g * 32], 0u);
            __threadfence();
            *gen = my + 1;
        } else {
            while (*gen == my) { }
        }
    }
    __syncthreads();
}

// ---------------- prep kernels ----------------
__global__ void to_f16v(const float4* __restrict__ s, uint2* __restrict__ o, long long n4) {
    long long i = (long long)blockIdx.x * blockDim.x + threadIdx.x;
    if (i < n4) {
        float4 v = s[i];
        __half2 a = __floats2half2_rn(v.x, v.y);
        __half2 b = __floats2half2_rn(v.z, v.w);
        uint2 r;
        r.x = *(uint32_t*)&a; r.y = *(uint32_t*)&b;
        o[i] = r;
    }
}
__global__ void bias_combine(const float* __restrict__ a, const float* __restrict__ b,
                             float* __restrict__ out, int n) {
    int i = blockIdx.x * blockDim.x + threadIdx.x;
    if (i < n) out[i] = a[i] + b[i];
}

// ================= fp16 HMMA pre-activation GEMM (1-pass, 3-stage) =================
#define PG_STAGE 32768
#define PG_SMEM  (3 * PG_STAGE)

__global__ void __launch_bounds__(256, 1)
gemm_mma(const __half* __restrict__ Af, const __half* __restrict__ Wf,
         const float* __restrict__ bias, float* __restrict__ C, int K) {
    extern __shared__ __align__(128) char smem[];
    const uint32_t sb = smem_u32(smem);
    const int tid = threadIdx.x, l = tid & 31, w = tid >> 5;
    const long long m0 = (long long)blockIdx.x * 128;
    const int n0 = blockIdx.y * 128;
    const int nch = K >> 6;

    const int r0 = tid >> 3, c = tid & 7;
    const uint32_t sd0 = (uint32_t)r0 * 128 + (((uint32_t)c * 16) ^ (((uint32_t)r0 & 7) * 16));

    const int m_off = (w & 3) * 32, n_off = (w >> 2) * 64;
    const int arw = m_off + (l & 7) + ((l & 8) ? 8 : 0);
    const uint32_t abase = (uint32_t)arw * 128;
    const uint32_t ax = ((uint32_t)arw & 7) * 16;
    const uint32_t akb = (l & 16) ? 16 : 0;
    const int brw = n_off + (l & 7) + ((l & 16) ? 8 : 0);
    const uint32_t bbase = (uint32_t)brw * 128;
    const uint32_t bx = ((uint32_t)brw & 7) * 16;
    const uint32_t bkb = (l & 8) ? 16 : 0;

    float acc[2][8][4];
#pragma unroll
    for (int i = 0; i < 2; i++)
#pragma unroll
        for (int j = 0; j < 8; j++)
#pragma unroll
            for (int k = 0; k < 4; k++) acc[i][j][k] = 0.0f;

    auto issue = [&](int kc) {
        const uint32_t d = sb + (uint32_t)(kc % 3) * PG_STAGE;
        const int ko = kc * 64 + c * 8;
#pragma unroll
        for (int j = 0; j < 4; ++j) {
            const long long ar = (m0 + r0 + 32 * j) * (long long)K + ko;
            const long long wr = ((long long)(n0 + r0 + 32 * j)) * K + ko;
            const uint32_t du = d + sd0 + j * 4096;
            CP16(du,          Af + ar);
            CP16(du + 16384,  Wf + wr);
        }
        CP_COMMIT();
    };

    issue(0);
    issue(1);

    for (int kc = 0; kc < nch; ++kc) {
        if (kc < nch - 1) CP_WAIT(1); else CP_WAIT(0);
        __syncthreads();
        if (kc + 2 < nch) issue(kc + 2);

        const uint32_t st = sb + (uint32_t)(kc % 3) * PG_STAGE;
#pragma unroll
        for (int ks = 0; ks < 4; ++ks) {
            uint32_t ah0[4], ah1[4];
            const uint32_t ao = ((uint32_t)(ks * 32) + akb) ^ ax;
            LDMX4(ah0, st + abase + ao);
            LDMX4(ah1, st + abase + 2048 + ao);
            uint32_t bh[4][4];
            const uint32_t bo = ((uint32_t)(ks * 32) + bkb) ^ bx;
#pragma unroll
            for (int nb = 0; nb < 4; ++nb)
                LDMX4(bh[nb], st + 16384 + bbase + nb * 2048 + bo);
#pragma unroll
            for (int nb = 0; nb < 4; ++nb) {
                MMAH16816(acc[0][2 * nb],     ah0, bh[nb][0], bh[nb][1]);
                MMAH16816(acc[0][2 * nb + 1], ah0, bh[nb][2], bh[nb][3]);
                MMAH16816(acc[1][2 * nb],     ah1, bh[nb][0], bh[nb][1]);
                MMAH16816(acc[1][2 * nb + 1], ah1, bh[nb][2], bh[nb][3]);
            }
        }
        __syncthreads();
    }

#pragma unroll
    for (int mf = 0; mf < 2; ++mf) {
        const long long R0 = m0 + m_off + mf * 16 + (l >> 2);
#pragma unroll
        for (int nf = 0; nf < 8; ++nf) {
            const int col = n0 + n_off + nf * 8 + (l & 3) * 2;
            const float2 bv = __ldg((const float2*)(bias + col));
            float2 o0, o1;
            o0.x = acc[mf][nf][0] + bv.x; o0.y = acc[mf][nf][1] + bv.y;
            o1.x = acc[mf][nf][2] + bv.x; o1.y = acc[mf][nf][3] + bv.y;
            __stcg((float2*)(C + R0 * HH + col), o0);
            __stcg((float2*)(C + (R0 + 8) * HH + col), o1);
        }
    }
}

// ================= FUSED layer-0 recurrence + pre1 GEMM =================
// grid 128 = 4 batch-groups(64 rows) x 32 H-tiles(32 cols). 512 threads, 1 CTA/SM.
// 16 warps = 2 mpos x 2 npos x 4 kslots. Warp tile 32m x 16n (rec AND pre1).
// W_hh0 resident @0 (64KB), W_ih1 resident @65536 (64KB).
// A (h1, 16KB/chunk) streamed: 8 chunks of 128-K, 3-stage ring @131072 (48KB).
// Dual 4-way K reduction through 64KB region overlapping the ring.
// Step t: computes h1_t = relu(pre0_t + h1_{t-1}@Whh0^T) AND pre1_{t-1} =
// h1_{t-1}@Wih1^T + bias1 from the same staged chunks. Tail iteration t=TT
// produces pre1_{TT-1}.
#define FW1   65536
#define FA_ST 131072
#define FA_STG 16384
#define FN_SMEM (FA_ST + 65536)   // 192KB

__global__ void __launch_bounds__(512, 1)
rnn_fused(const float* __restrict__ pre0,
          __half* __restrict__ hseq,
          float* __restrict__ pre1out,
          const float* __restrict__ bias1) {
    extern __shared__ __align__(128) char smem[];
    const uint32_t sb = smem_u32(smem);
    const int tid = threadIdx.x, l = tid & 31, w = tid >> 5;
    const int grp = blockIdx.x & 3;
    const int m0 = grp * 64;
    const int n0 = (blockIdx.x >> 2) * 32;

    // resident W_hh0 and W_ih1: 16 blocks of [32 rows][128B] each (4KB blocks)
    for (int u = tid; u < 4096; u += 512) {
        const int blk = u >> 8, rem = u & 255, r = rem >> 3, cc = rem & 7;
        const uint32_t dst = (uint32_t)blk * 4096 + (uint32_t)r * 128 +
                             (((uint32_t)cc * 16) ^ (((uint32_t)r & 7) * 16));
        const long long src = (long long)(n0 + r) * HH + blk * 64 + cc * 8;
        *(uint4*)(smem + dst)       = *(const uint4*)(g_whh0 + src);
        *(uint4*)(smem + FW1 + dst) = *(const uint4*)(g_wih1 + src);
    }
    __syncthreads();

    // staging: per 128-K chunk, A = 2 sub-blocks x [64 rows][128B] (8KB each).
    // thread stages rows srr (0..63), 16B-col scc in both sub-blocks.
    const int srr = tid >> 3, scc = tid & 7;
    const uint32_t st0 = (uint32_t)srr * 128 + (((uint32_t)scc * 16) ^ (((uint32_t)srr & 7) * 16));

    // compute mapping: 16 warps = mpos(2) x npos(2) x kslot(4)
    const int mpos = w & 1;
    const int npos = (w >> 1) & 1;
    const int kslot = w >> 2;          // 0..3: k16 slice within each 64-K sub-block
    const uint32_t ax = ((uint32_t)l & 7) * 16;
    const uint32_t akb = (l & 16) ? 16u : 0u;
    const uint32_t a0base = (uint32_t)(mpos * 32 + (l & 15)) * 128;
    const uint32_t bkb = (l & 8) ? 16u : 0u;
    const uint32_t b0base = (uint32_t)(npos * 16 + (l & 7) + ((l & 16) ? 8 : 0)) * 128;
    const uint32_t kob = (uint32_t)(kslot * 32);
    const uint32_t ao = (kob + akb) ^ ax;
    const uint32_t bo = (kob + bkb) ^ ax;
    const uint32_t wblkbase = (uint32_t)((mpos * 2 + npos) * 4 + kslot) * 4096;

    // reduce/epilogue mapping: tid = mpos'(1) npos'(1) L(5) q(2)
    const int rmp = tid >> 8;
    const int rnp = (tid >> 7) & 1;
    const int rl = (tid >> 2) & 31;
    const int q = tid & 3;             // = mf*2 + nf
    const int erow = m0 + rmp * 32 + (q >> 1) * 16 + (rl >> 2);
    const int ecol = n0 + rnp * 16 + (q & 1) * 8 + (rl & 3) * 2;
    const uint32_t rbase0 = (uint32_t)((rmp * 2 + rnp) * 4) * 4096 + (uint32_t)rl * 128;
    const uint32_t rs_rec = ((uint32_t)q ^ ((uint32_t)rl & 7)) * 16;
    const uint32_t rs_pre = ((uint32_t)(4 + q) ^ ((uint32_t)rl & 7)) * 16;
    const float2 b1v = __ldg((const float2*)(bias1 + ecol));

    for (int t = 0; t <= TT; ++t) {
        float2 p0, p1;
        if (t < TT) {
            p0 = __ldcg((const float2*)(pre0 + ((long long)erow * TT + t) * HH + ecol));
            p1 = __ldcg((const float2*)(pre0 + ((long long)(erow + 8) * TT + t) * HH + ecol));
        }

        float ar[2][2][4], ap[2][2][4];
#pragma unroll
        for (int i = 0; i < 2; i++)
#pragma unroll
            for (int j = 0; j < 2; j++)
#pragma unroll
                for (int k = 0; k < 4; k++) { ar[i][j][k] = 0.0f; ap[i][j][k] = 0.0f; }

        if (t > 0) {
            const long long ab = ((long long)(m0 + srr) * TT + (t - 1)) * HH + scc * 8;

            auto issueA = [&](int cix) {
                const uint32_t d = sb + FA_ST + (uint32_t)(cix % 3) * FA_STG;
                CP16(d + st0,        hseq + ab + cix * 128);
                CP16(d + 8192 + st0, hseq + ab + cix * 128 + 64);
                CP_COMMIT();
            };

            issueA(0);
            issueA(1);

            for (int cix = 0; cix < 8; ++cix) {
                if (cix < 7) CP_WAIT(1); else CP_WAIT(0);
                __syncthreads();
                if (cix + 2 < 8) issueA(cix + 2);

                const uint32_t stg = sb + FA_ST + (uint32_t)(cix % 3) * FA_STG;
#pragma unroll
                for (int subi = 0; subi < 2; ++subi) {
                    const uint32_t ahbuf = stg + (uint32_t)subi * 8192;
                    const uint32_t wblk = (uint32_t)(2 * cix + subi) * 4096;
                    uint32_t ah0[4], ah1[4], br[4], bp[4];
                    LDMX4(ah0, ahbuf + a0base + ao);
                    LDMX4(ah1, ahbuf + a0base + 2048 + ao);
                    LDMX4(br, sb + wblk + b0base + bo);
                    LDMX4(bp, sb + FW1 + wblk + b0base + bo);
                    MMAH16816(ar[0][0], ah0, br[0], br[1]); MMAH16816(ar[0][1], ah0, br[2], br[3]);
                    MMAH16816(ar[1][0], ah1, br[0], br[1]); MMAH16816(ar[1][1], ah1, br[2], br[3]);
                    MMAH16816(ap[0][0], ah0, bp[0], bp[1]); MMAH16816(ap[0][1], ah0, bp[2], bp[3]);
                    MMAH16816(ap[1][0], ah1, bp[0], bp[1]); MMAH16816(ap[1][1], ah1, bp[2], bp[3]);
                }
            }
        }

        // ---- dual 4-way K reduction through smem ----
        __syncthreads();
        {
            char* wp = smem + FA_ST + wblkbase + l * 128;
            const uint32_t lsw = (uint32_t)l & 7;
#pragma unroll
            for (int mf = 0; mf < 2; ++mf)
#pragma unroll
                for (int nf = 0; nf < 2; ++nf) {
                    const uint32_t j = (uint32_t)(mf * 2 + nf);
                    *(float4*)(wp + ((j ^ lsw) * 16))       = *(float4*)ar[mf][nf];
                    *(float4*)(wp + (((4 + j) ^ lsw) * 16)) = *(float4*)ap[mf][nf];
                }
        }
        __syncthreads();
        float sr[4] = {0.f, 0.f, 0.f, 0.f};
        float sp[4] = {0.f, 0.f, 0.f, 0.f};
#pragma unroll
        for (int k = 0; k < 4; ++k) {
            const char* rp = smem + FA_ST + rbase0 + (uint32_t)k * 4096;
            const float4 u = *(const float4*)(rp + rs_rec);
            const float4 v = *(const float4*)(rp + rs_pre);
            sr[0] += u.x; sr[1] += u.y; sr[2] += u.z; sr[3] += u.w;
            sp[0] += v.x; sp[1] += v.y; sp[2] += v.z; sp[3] += v.w;
        }

        // ---- rec epilogue: h_t = relu(sr + pre0_t) ----
        if (t < TT) {
            const long long R0 = erow, R1 = erow + 8;
            float v0 = fmaxf(sr[0] + p0.x, 0.0f);
            float v1 = fmaxf(sr[1] + p0.y, 0.0f);
            float v2 = fmaxf(sr[2] + p1.x, 0.0f);
            float v3 = fmaxf(sr[3] + p1.y, 0.0f);
            __half2 ha = __floats2half2_rn(v0, v1);
            __half2 hb = __floats2half2_rn(v2, v3);
            __stcg((uint32_t*)(hseq + (R0 * TT + t) * HH + ecol), *(uint32_t*)&ha);
            __stcg((uint32_t*)(hseq + (R1 * TT + t) * HH + ecol), *(uint32_t*)&hb);
        }
        // ---- pre1 epilogue: pre1_{t-1} = sp + bias1 ----
        if (t > 0) {
            const long long R0 = erow, R1 = erow + 8;
            __stcg((float2*)(pre1out + (R0 * TT + (t - 1)) * HH + ecol),
                   make_float2(sp[0] + b1v.x, sp[1] + b1v.y));
            __stcg((float2*)(pre1out + (R1 * TT + (t - 1)) * HH + ecol),
                   make_float2(sp[2] + b1v.x, sp[3] + b1v.y));
        }
        if (t < TT) grid_bar_g(grp);
    }
}

// ================= plain recurrence (R12, layer 1) =================
#define RA_ST 65536
#define RA_STG 8192
#define RN_SMEM (RA_ST + 32768)

__global__ void __launch_bounds__(256, 2)
rnn_mma(const __half* __restrict__ Wf, const float* __restrict__ pre,
        __half* __restrict__ hpp, float* __restrict__ hfin) {
    extern __shared__ __align__(128) char smem[];
    const uint32_t sb = smem_u32(smem);
    const int tid = threadIdx.x, l = tid & 31, w = tid >> 5;
    const int grp = blockIdx.x & 7;
    const int m0 = grp * 32;
    const int n0 = (blockIdx.x >> 3) * 32;

    for (int u = tid; u < 4096; u += 256) {
        const int kc = u >> 8, rem = u & 255, r = rem >> 3, cc = rem & 7;
        const uint32_t dst = (uint32_t)kc * 4096 + (uint32_t)r * 128 +
                             (((uint32_t)cc * 16) ^ (((uint32_t)r & 7) * 16));
        const long long src = (long long)(n0 + r) * HH + kc * 64 + cc * 8;
        *(uint4*)(smem + dst) = *(const uint4*)(Wf + src);
    }
    __syncthreads();

    const int srr = tid >> 3, scc = tid & 7;
    const uint32_t st0 = (uint32_t)srr * 128 + (((uint32_t)scc * 16) ^ (((uint32_t)srr & 7) * 16));

    const int kslot = w;
    const int bsel = kslot >> 2;
    const int si = kslot & 3;
    const uint32_t ax = ((uint32_t)l & 7) * 16;
    const uint32_t akb = (l & 16) ? 16u : 0u;
    const uint32_t a0base = (uint32_t)(l & 15) * 128;
    const uint32_t bkb = (l & 8) ? 16u : 0u;
    const uint32_t b0base = (uint32_t)((l & 7) + ((l & 16) ? 8 : 0)) * 128;
    const uint32_t kob = (uint32_t)(si * 32);
    const uint32_t ao = (kob + akb) ^ ax;
    const uint32_t bo = (kob + bkb) ^ ax;

    const int rl = tid >> 3;
    const int rfg = tid & 7;
    const int erow = m0 + (rfg >> 2) * 16 + (rl >> 2);
    const int ecol = n0 + (rfg & 3) * 8 + (rl & 3) * 2;
    const uint32_t rsw = ((uint32_t)rfg * 16) ^ (((uint32_t)rl & 7) * 16);

    for (int t = 0; t < TT; ++t) {
        float2 p0 = __ldcg((const float2*)(pre + ((long long)erow * TT + t) * HH + ecol));
        float2 p1 = __ldcg((const float2*)(pre + ((long long)(erow + 8) * TT + t) * HH + ecol));

        float acc[2][4][4];
#pragma unroll
        for (int i = 0; i < 2; i++)
#pragma unroll
            for (int j = 0; j < 4; j++)
#pragma unroll
                for (int k = 0; k < 4; k++) acc[i][j][k] = 0.0f;

        if (t > 0) {
            const long long ab = (long long)((t - 1) & 1) * BB * HH +
                                 (long long)(m0 + srr) * HH + scc * 8;

            auto issueA = [&](int cix) {
                const uint32_t d = sb + RA_ST + (uint32_t)(cix % 3) * RA_STG;
                CP16(d + st0,        hpp + ab + cix * 128);
                CP16(d + 4096 + st0, hpp + ab + cix * 128 + 64);
                CP_COMMIT();
            };

            issueA(0);
            issueA(1);

            for (int cix = 0; cix < 8; ++cix) {
                if (cix < 7) CP_WAIT(1); else CP_WAIT(0);
                __syncthreads();
                if (cix + 2 < 8) issueA(cix + 2);

                const uint32_t stg = sb + RA_ST + (uint32_t)(cix % 3) * RA_STG;
                const uint32_t ahbuf = stg + (uint32_t)bsel * 4096;
                const uint32_t bhbuf = sb + (uint32_t)(2 * cix + bsel) * 4096;

                uint32_t ah0[4], ah1[4], bh0[4], bh1[4];
                LDMX4(ah0, ahbuf + a0base + ao);
                LDMX4(ah1, ahbuf + a0base + 2048 + ao);
                LDMX4(bh0, bhbuf + b0base + bo);
                LDMX4(bh1, bhbuf + b0base + 2048 + bo);
                MMAH16816(acc[0][0], ah0, bh0[0], bh0[1]); MMAH16816(acc[0][1], ah0, bh0[2], bh0[3]);
                MMAH16816(acc[0][2], ah0, bh1[0], bh1[1]); MMAH16816(acc[0][3], ah0, bh1[2], bh1[3]);
                MMAH16816(acc[1][0], ah1, bh0[0], bh0[1]); MMAH16816(acc[1][1], ah1, bh0[2], bh0[3]);
                MMAH16816(acc[1][2], ah1, bh1[0], bh1[1]); MMAH16816(acc[1][3], ah1, bh1[2], bh1[3]);
            }
        }

        __syncthreads();
        {
            char* wp = smem + RA_ST + kslot * 4096 + l * 128;
            const uint32_t wsw = ((uint32_t)l & 7) * 16;
#pragma unroll
            for (int mf = 0; mf < 2; ++mf)
#pragma unroll
                for (int nf = 0; nf < 4; ++nf)
                    *(float4*)(wp + (((uint32_t)(mf * 4 + nf) * 16) ^ wsw)) = *(float4*)acc[mf][nf];
        }
        __syncthreads();
        float s[4] = {0.f, 0.f, 0.f, 0.f};
#pragma unroll
        for (int k = 0; k < 8; ++k) {
            const float4 u = *(const float4*)(smem + RA_ST + k * 4096 + rl * 128 + rsw);
            s[0] += u.x; s[1] += u.y; s[2] += u.z; s[3] += u.w;
        }

        {
            const long long R0 = erow, R1 = erow + 8;
            float v0 = fmaxf(s[0] + p0.x, 0.0f);
            float v1 = fmaxf(s[1] + p0.y, 0.0f);
            float v2 = fmaxf(s[2] + p1.x, 0.0f);
            float v3 = fmaxf(s[3] + p1.y, 0.0f);
            __half2 ha = __floats2half2_rn(v0, v1);
            __half2 hb = __floats2half2_rn(v2, v3);
            const long long ob0 = (long long)(t & 1) * BB * HH + R0 * HH + ecol;
            const long long ob1 = (long long)(t & 1) * BB * HH + R1 * HH + ecol;
            __stcg((uint32_t*)(hpp + ob0), *(uint32_t*)&ha);
            __stcg((uint32_t*)(hpp + ob1), *(uint32_t*)&hb);
            if (t == TT - 1) {
                __stcg((float2*)(hfin + R0 * HH + ecol), make_float2(v0, v1));
                __stcg((float2*)(hfin + R1 * HH + ecol), make_float2(v2, v3));
            }
        }
        grid_bar_g(grp);
    }
}

// ---------------- small scalar GEMM for fc ----------------
template <int BM, int BN, int TM, int TN>
__global__ void __launch_bounds__((BM / TM) * (BN / TN))
gemm_nt(const float* __restrict__ A, long long a_stride,
        const float* __restrict__ W, const float* __restrict__ bias,
        float* __restrict__ C, long long c_stride, int K) {
    constexpr int BK = 16, TX = BN / TN, TY = BM / TM, NT = TX * TY;
    __shared__ __align__(16) float As[BK][BM];
    __shared__ __align__(16) float Ws[BK][BN];
    const int tid = threadIdx.x, tx = tid % TX, ty = tid / TX;
    const long long m0 = (long long)blockIdx.x * BM;
    const int n0 = blockIdx.y * BN;
    float acc[TM][TN];
#pragma unroll
    for (int i = 0; i < TM; i++)
#pragma unroll
        for (int j = 0; j < TN; j++) acc[i][j] = 0.0f;
    for (int kt = 0; kt < K; kt += BK) {
#pragma unroll
        for (int idx = tid; idx < BM * 4; idx += NT) {
            const int row = idx >> 2, kq = (idx & 3) * 4;
            const float4 v = *(const float4*)(A + (m0 + row) * a_stride + kt + kq);
            As[kq][row] = v.x; As[kq + 1][row] = v.y; As[kq + 2][row] = v.z; As[kq + 3][row] = v.w;
        }
#pragma unroll
        for (int idx = tid; idx < BN * 4; idx += NT) {
            const int row = idx >> 2, kq = (idx & 3) * 4;
            const float4 v = *(const float4*)(W + (long long)(n0 + row) * K + kt + kq);
            Ws[kq][row] = v.x; Ws[kq + 1][row] = v.y; Ws[kq + 2][row] = v.z; Ws[kq + 3][row] = v.w;
        }
        __syncthreads();
#pragma unroll
        for (int kk = 0; kk < BK; kk++) {
            float a[TM], b[TN];
#pragma unroll
            for (int i = 0; i < TM; i += 4) {
                const float4 v = *(const float4*)&As[kk][ty * TM + i];
                a[i] = v.x; a[i + 1] = v.y; a[i + 2] = v.z; a[i + 3] = v.w;
            }
#pragma unroll
            for (int j = 0; j < TN; j += 4) {
                const float4 v = *(const float4*)&Ws[kk][tx * TN + j];
                b[j] = v.x; b[j + 1] = v.y; b[j + 2] = v.z; b[j + 3] = v.w;
            }
#pragma unroll
            for (int i = 0; i < TM; i++)
#pragma unroll
                for (int j = 0; j < TN; j++) acc[i][j] = fmaf(a[i], b[j], acc[i][j]);
        }
        __syncthreads();
    }
#pragma unroll
    for (int i = 0; i < TM; i++) {
        const long long m = m0 + ty * TM + i;
#pragma unroll
        for (int j = 0; j < TN; j++)
            C[m * c_stride + n0 + tx * TN + j] = acc[i][j] + bias[n0 + tx * TN + j];
    }
}

// ---------------- launch ----------------
extern "C" void kernel_launch(void* const* d_in, const int* in_sizes, int n_in,
                              void* d_out, int out_size) {
    const float* x     = (const float*)d_in[0];
    const float* W_ih0 = (const float*)d_in[1];
    const float* W_hh0 = (const float*)d_in[2];
    const float* b_ih0 = (const float*)d_in[3];
    const float* b_hh0 = (const float*)d_in[4];
    const float* W_ih1 = (const float*)d_in[5];
    const float* W_hh1 = (const float*)d_in[6];
    const float* b_ih1 = (const float*)d_in[7];
    const float* b_hh1 = (const float*)d_in[8];
    const float* fc_w  = (const float*)d_in[9];
    const float* fc_b  = (const float*)d_in[10];
    float* out = (float*)d_out;

    float *p_pre, *p_pre2, *p_b0, *p_b1, *p_h2f;
    __half *p_xf, *p_h1f, *p_h2f16;
    __half *p_wih0, *p_wih1, *p_whh0, *p_whh1;
    cudaGetSymbolAddress((void**)&p_pre, g_pre);
    cudaGetSymbolAddress((void**)&p_pre2, g_pre2);
    cudaGetSymbolAddress((void**)&p_b0, g_bias0);
    cudaGetSymbolAddress((void**)&p_b1, g_bias1);
    cudaGetSymbolAddress((void**)&p_h2f, g_h2f);
    cudaGetSymbolAddress((void**)&p_xf, g_xf);
    cudaGetSymbolAddress((void**)&p_h1f, g_h1f);
    cudaGetSymbolAddress((void**)&p_h2f16, g_h2f16);
    cudaGetSymbolAddress((void**)&p_wih0, g_wih0);
    cudaGetSymbolAddress((void**)&p_wih1, g_wih1);
    cudaGetSymbolAddress((void**)&p_whh0, g_whh0);
    cudaGetSymbolAddress((void**)&p_whh1, g_whh1);

    cudaFuncSetAttribute(gemm_mma, cudaFuncAttributeMaxDynamicSharedMemorySize, PG_SMEM);
    cudaFuncSetAttribute(rnn_fused, cudaFuncAttributeMaxDynamicSharedMemorySize, FN_SMEM);
    cudaFuncSetAttribute(rnn_mma, cudaFuncAttributeMaxDynamicSharedMemorySize, RN_SMEM);

    const long long nx4 = (long long)BB * TT * II / 4;
    const long long nw04 = (long long)HH * II / 4;
    const long long nw4 = (long long)HH * HH / 4;

    // prep
    to_f16v<<<(unsigned)((nx4 + 255) / 256), 256>>>((const float4*)x, (uint2*)p_xf, nx4);
    to_f16v<<<(unsigned)((nw04 + 255) / 256), 256>>>((const float4*)W_ih0, (uint2*)p_wih0, nw04);
    bias_combine<<<(HH + 255) / 256, 256>>>(b_ih0, b_hh0, p_b0, HH);
    to_f16v<<<(unsigned)((nw4 + 255) / 256), 256>>>((const float4*)W_hh0, (uint2*)p_whh0, nw4);
    to_f16v<<<(unsigned)((nw4 + 255) / 256), 256>>>((const float4*)W_ih1, (uint2*)p_wih1, nw4);
    bias_combine<<<(HH + 255) / 256, 256>>>(b_ih1, b_hh1, p_b1, HH);
    // pre0 = x @ W_ih0^T + bias0
    gemm_mma<<<dim3((BB * TT) / 128, HH / 128), 256, PG_SMEM>>>(
        p_xf, p_wih0, p_b0, p_pre, II);
    // fused layer-0 recurrence + pre1 GEMM
    rnn_fused<<<128, 512, FN_SMEM>>>(p_pre, p_h1f, p_pre2, p_b1);
    // W_hh1 -> fp16
    to_f16v<<<(unsigned)((nw4 + 255) / 256), 256>>>((const float4*)W_hh1, (uint2*)p_whh1, nw4);
    // layer-1 recurrence (plain, ping-pong)
    rnn_mma<<<256, 256, RN_SMEM>>>(p_whh1, p_pre2, p_h2f16, p_h2f);
    // fc
    gemm_nt<32, 64, 4, 4><<<dim3(BB / 32, OO / 64), 128>>>(
        p_h2f, HH, fc_w, fc_b, out, OO, HH);
}

// round 15
// speedup vs baseline: 1.4364x; 1.1633x over previous
#include <cuda_runtime.h>
#include <cuda_fp16.h>
#include <cstdint>

// ---------------- problem dims ----------------
#define BB 256
#define TT 512
#define II 512
#define HH 1024
#define OO 256

// ---------------- static device scratch (allocation-free) ----------------
__device__ __align__(16) float g_pre[BB * TT * HH];          // pre0
__device__ __align__(16) __half g_xf[BB * TT * II];
__device__ __align__(16) __half g_h1f[BB * TT * HH];         // layer0 hidden seq fp16
__device__ __align__(16) __half g_h2f16[2 * BB * HH];        // layer1 ping-pong fp16
__device__ __align__(16) float g_h2f[BB * HH];               // layer1 final fp32
__device__ __align__(16) __half g_wih0[HH * II];
__device__ __align__(16) __half g_wih1[HH * HH];
__device__ __align__(16) __half g_whh0[HH * HH];
__device__ __align__(16) __half g_whh1[HH * HH];
__device__ __align__(16) float g_bias0[HH];
__device__ __align__(16) float g_bias1[HH];
__device__ unsigned g_cnt2[256];
__device__ unsigned g_gen2[256];

// ---------------- PTX helpers (baseline PTX only) ----------------
__device__ __forceinline__ uint32_t smem_u32(const void* p) {
    uint32_t a;
    asm("{ .reg .u64 t; cvta.to.shared.u64 t, %1; cvt.u32.u64 %0, t; }" : "=r"(a) : "l"(p));
    return a;
}
#define CP16(dst, src) \
    asm volatile("cp.async.cg.shared.global [%0], [%1], 16;" :: "r"(dst), "l"(src) : "memory")
#define CP_COMMIT() asm volatile("cp.async.commit_group;" ::: "memory")
#define CP_WAIT(n)  asm volatile("cp.async.wait_group %0;" :: "n"(n) : "memory")

#define LDMX4(r, addr) \
    asm volatile("ldmatrix.sync.aligned.m8n8.x4.shared.b16 {%0,%1,%2,%3}, [%4];" \
                 : "=r"((r)[0]), "=r"((r)[1]), "=r"((r)[2]), "=r"((r)[3]) : "r"(addr))

#define MMAH16816(d, a, b0, b1) \
    asm volatile("mma.sync.aligned.m16n8k16.row.col.f32.f16.f16.f32 " \
                 "{%0,%1,%2,%3},{%4,%5,%6,%7},{%8,%9},{%0,%1,%2,%3};" \
                 : "+f"((d)[0]), "+f"((d)[1]), "+f"((d)[2]), "+f"((d)[3]) \
                 : "r"((a)[0]), "r"((a)[1]), "r"((a)[2]), "r"((a)[3]), "r"(b0), "r"(b1))

// ---------------- group grid barrier (32 CTAs per group) ----------------
__device__ __forceinline__ void grid_bar_g(int g) {
    __threadfence();
    __syncthreads();
    if (threadIdx.x == 0) {
        volatile unsigned* gen = (volatile unsigned*)&g_gen2[g * 32];
        unsigned my = *gen;
        if (atomicAdd(&g_cnt2[g * 32], 1u) == 31u) {
            atomicExch(&g_cnt2[g * 32], 0u);
            __threadfence();
            *gen = my + 1;
        } else {
            while (*gen == my) { }
        }
    }
    __syncthreads();
}

// ---------------- prep kernels ----------------
__global__ void to_f16v(const float4* __restrict__ s, uint2* __restrict__ o, long long n4) {
    long long i = (long long)blockIdx.x * blockDim.x + threadIdx.x;
    if (i < n4) {
        float4 v = s[i];
        __half2 a = __floats2half2_rn(v.x, v.y);
        __half2 b = __floats2half2_rn(v.z, v.w);
        uint2 r;
        r.x = *(uint32_t*)&a; r.y = *(uint32_t*)&b;
        o[i] = r;
    }
}
__global__ void bias_combine(const float* __restrict__ a, const float* __restrict__ b,
                             float* __restrict__ out, int n) {
    int i = blockIdx.x * blockDim.x + threadIdx.x;
    if (i < n) out[i] = a[i] + b[i];
}

// ================= fp16 HMMA pre-activation GEMM (pre0 only) =================
#define PG_STAGE 32768
#define PG_SMEM  (3 * PG_STAGE)

__global__ void __launch_bounds__(256, 1)
gemm_mma(const __half* __restrict__ Af, const __half* __restrict__ Wf,
         const float* __restrict__ bias, float* __restrict__ C, int K) {
    extern __shared__ __align__(128) char smem[];
    const uint32_t sb = smem_u32(smem);
    const int tid = threadIdx.x, l = tid & 31, w = tid >> 5;
    const long long m0 = (long long)blockIdx.x * 128;
    const int n0 = blockIdx.y * 128;
    const int nch = K >> 6;

    const int r0 = tid >> 3, c = tid & 7;
    const uint32_t sd0 = (uint32_t)r0 * 128 + (((uint32_t)c * 16) ^ (((uint32_t)r0 & 7) * 16));

    const int m_off = (w & 3) * 32, n_off = (w >> 2) * 64;
    const int arw = m_off + (l & 7) + ((l & 8) ? 8 : 0);
    const uint32_t abase = (uint32_t)arw * 128;
    const uint32_t ax = ((uint32_t)arw & 7) * 16;
    const uint32_t akb = (l & 16) ? 16 : 0;
    const int brw = n_off + (l & 7) + ((l & 16) ? 8 : 0);
    const uint32_t bbase = (uint32_t)brw * 128;
    const uint32_t bx = ((uint32_t)brw & 7) * 16;
    const uint32_t bkb = (l & 8) ? 16 : 0;

    float acc[2][8][4];
#pragma unroll
    for (int i = 0; i < 2; i++)
#pragma unroll
        for (int j = 0; j < 8; j++)
#pragma unroll
            for (int k = 0; k < 4; k++) acc[i][j][k] = 0.0f;

    auto issue = [&](int kc) {
        const uint32_t d = sb + (uint32_t)(kc % 3) * PG_STAGE;
        const int ko = kc * 64 + c * 8;
#pragma unroll
        for (int j = 0; j < 4; ++j) {
            const long long ar = (m0 + r0 + 32 * j) * (long long)K + ko;
            const long long wr = ((long long)(n0 + r0 + 32 * j)) * K + ko;
            const uint32_t du = d + sd0 + j * 4096;
            CP16(du,          Af + ar);
            CP16(du + 16384,  Wf + wr);
        }
        CP_COMMIT();
    };

    issue(0);
    issue(1);

    for (int kc = 0; kc < nch; ++kc) {
        if (kc < nch - 1) CP_WAIT(1); else CP_WAIT(0);
        __syncthreads();
        if (kc + 2 < nch) issue(kc + 2);

        const uint32_t st = sb + (uint32_t)(kc % 3) * PG_STAGE;
#pragma unroll
        for (int ks = 0; ks < 4; ++ks) {
            uint32_t ah0[4], ah1[4];
            const uint32_t ao = ((uint32_t)(ks * 32) + akb) ^ ax;
            LDMX4(ah0, st + abase + ao);
            LDMX4(ah1, st + abase + 2048 + ao);
            uint32_t bh[4][4];
            const uint32_t bo = ((uint32_t)(ks * 32) + bkb) ^ bx;
#pragma unroll
            for (int nb = 0; nb < 4; ++nb)
                LDMX4(bh[nb], st + 16384 + bbase + nb * 2048 + bo);
#pragma unroll
            for (int nb = 0; nb < 4; ++nb) {
                MMAH16816(acc[0][2 * nb],     ah0, bh[nb][0], bh[nb][1]);
                MMAH16816(acc[0][2 * nb + 1], ah0, bh[nb][2], bh[nb][3]);
                MMAH16816(acc[1][2 * nb],     ah1, bh[nb][0], bh[nb][1]);
                MMAH16816(acc[1][2 * nb + 1], ah1, bh[nb][2], bh[nb][3]);
            }
        }
        __syncthreads();
    }

#pragma unroll
    for (int mf = 0; mf < 2; ++mf) {
        const long long R0 = m0 + m_off + mf * 16 + (l >> 2);
#pragma unroll
        for (int nf = 0; nf < 8; ++nf) {
            const int col = n0 + n_off + nf * 8 + (l & 3) * 2;
            const float2 bv = __ldg((const float2*)(bias + col));
            float2 o0, o1;
            o0.x = acc[mf][nf][0] + bv.x; o0.y = acc[mf][nf][1] + bv.y;
            o1.x = acc[mf][nf][2] + bv.x; o1.y = acc[mf][nf][3] + bv.y;
            __stcg((float2*)(C + R0 * HH + col), o0);
            __stcg((float2*)(C + (R0 + 8) * HH + col), o1);
        }
    }
}

// ================= PIPELINED both-layer recurrence =================
// 128 CTAs (4 grp x 32 ntile), 512 thr, 1 CTA/SM (all resident).
// Resident: W_hh0@0, W_ih1@64K, W_hh1@128K (64KB each, 16 blocks [32r][128B]).
// Ring @192K: 2 stages x 16KB (A chunk = 2x[64r][128B]); reduce region overlaps.
// Tick t (0..TT): Phase A = layer0 step t (rec0 + pre1_{t-1}, pre1 stays in
// registers); Phase B = layer1 step u=t-1 using this tick's pre1. One barrier.
#define PW1 65536
#define PW2 131072
#define PRING 196608
#define PSTG 16384
#define PN_SMEM (PRING + 32768)   // 224KB

__global__ void __launch_bounds__(512, 1)
rnn_pipe(const float* __restrict__ pre0,
         __half* __restrict__ h0seq,
         __half* __restrict__ h1pp,
         float* __restrict__ hfin,
         const float* __restrict__ bias1) {
    extern __shared__ __align__(128) char smem[];
    const uint32_t sb = smem_u32(smem);
    const int tid = threadIdx.x, l = tid & 31, w = tid >> 5;
    const int grp = blockIdx.x & 3;
    const int m0 = grp * 64;
    const int n0 = (blockIdx.x >> 2) * 32;

    for (int u = tid; u < 4096; u += 512) {
        const int blk = u >> 8, rem = u & 255, r = rem >> 3, cc = rem & 7;
        const uint32_t dst = (uint32_t)blk * 4096 + (uint32_t)r * 128 +
                             (((uint32_t)cc * 16) ^ (((uint32_t)r & 7) * 16));
        const long long src = (long long)(n0 + r) * HH + blk * 64 + cc * 8;
        *(uint4*)(smem + dst)       = *(const uint4*)(g_whh0 + src);
        *(uint4*)(smem + PW1 + dst) = *(const uint4*)(g_wih1 + src);
        *(uint4*)(smem + PW2 + dst) = *(const uint4*)(g_whh1 + src);
    }
    __syncthreads();

    const int srr = tid >> 3, scc = tid & 7;
    const uint32_t st0 = (uint32_t)srr * 128 + (((uint32_t)scc * 16) ^ (((uint32_t)srr & 7) * 16));

    const int mpos = w & 1, npos = (w >> 1) & 1, kslot = w >> 2;
    const uint32_t ax = ((uint32_t)l & 7) * 16;
    const uint32_t akb = (l & 16) ? 16u : 0u;
    const uint32_t a0base = (uint32_t)(mpos * 32 + (l & 15)) * 128;
    const uint32_t bkb = (l & 8) ? 16u : 0u;
    const uint32_t b0base = (uint32_t)(npos * 16 + (l & 7) + ((l & 16) ? 8 : 0)) * 128;
    const uint32_t kob = (uint32_t)(kslot * 32);
    const uint32_t ao = (kob + akb) ^ ax;
    const uint32_t bo = (kob + bkb) ^ ax;
    const uint32_t wblk2 = (uint32_t)((mpos * 2 + npos) * 4 + kslot) * 2048;
    const uint32_t wlsw = ((uint32_t)l & 3) ^ (((uint32_t)l >> 2) & 3);

    const int rmp = tid >> 8, rnp = (tid >> 7) & 1, rl = (tid >> 2) & 31, q = tid & 3;
    const int erow = m0 + rmp * 32 + (q >> 1) * 16 + (rl >> 2);
    const int ecol = n0 + rnp * 16 + (q & 1) * 8 + (rl & 3) * 2;
    const uint32_t rquad = (uint32_t)((rmp * 2 + rnp) * 4) * 2048 + (uint32_t)rl * 64;
    const uint32_t rslot = (((uint32_t)q ^ ((uint32_t)rl & 3) ^ (((uint32_t)rl >> 2) & 3)) & 3) * 16;
    const float2 b1v = __ldg((const float2*)(bias1 + ecol));

    for (int t = 0; t <= TT; ++t) {
        float2 p0, p1;
        if (t < TT) {
            p0 = __ldcg((const float2*)(pre0 + ((long long)erow * TT + t) * HH + ecol));
            p1 = __ldcg((const float2*)(pre0 + ((long long)(erow + 8) * TT + t) * HH + ecol));
        }

        float ar[2][2][4], ap[2][2][4];
#pragma unroll
        for (int i = 0; i < 2; i++)
#pragma unroll
            for (int j = 0; j < 2; j++)
#pragma unroll
                for (int k = 0; k < 4; k++) { ar[i][j][k] = 0.0f; ap[i][j][k] = 0.0f; }

        // ---- Phase A: layer0 step t (rec0 + pre1) ----
        if (t >= 1) {
            const long long ab = ((long long)(m0 + srr) * TT + (t - 1)) * HH + scc * 8;
            {
                const uint32_t d = sb + PRING;
                CP16(d + st0,        h0seq + ab);
                CP16(d + 8192 + st0, h0seq + ab + 64);
                CP_COMMIT();
            }
            for (int cix = 0; cix < 8; ++cix) {
                CP_WAIT(0);
                __syncthreads();
                if (cix + 1 < 8) {
                    const uint32_t d = sb + PRING + (uint32_t)((cix + 1) & 1) * PSTG;
                    CP16(d + st0,        h0seq + ab + (cix + 1) * 128);
                    CP16(d + 8192 + st0, h0seq + ab + (cix + 1) * 128 + 64);
                    CP_COMMIT();
                }
                const uint32_t stg = sb + PRING + (uint32_t)(cix & 1) * PSTG;
#pragma unroll
                for (int subi = 0; subi < 2; ++subi) {
                    const uint32_t ahbuf = stg + (uint32_t)subi * 8192;
                    const uint32_t wblk = (uint32_t)(2 * cix + subi) * 4096;
                    uint32_t ah0[4], ah1[4], br[4], bp[4];
                    LDMX4(ah0, ahbuf + a0base + ao);
                    LDMX4(ah1, ahbuf + a0base + 2048 + ao);
                    LDMX4(br, sb + wblk + b0base + bo);
                    LDMX4(bp, sb + PW1 + wblk + b0base + bo);
                    MMAH16816(ar[0][0], ah0, br[0], br[1]); MMAH16816(ar[0][1], ah0, br[2], br[3]);
                    MMAH16816(ar[1][0], ah1, br[0], br[1]); MMAH16816(ar[1][1], ah1, br[2], br[3]);
                    MMAH16816(ap[0][0], ah0, bp[0], bp[1]); MMAH16816(ap[0][1], ah0, bp[2], bp[3]);
                    MMAH16816(ap[1][0], ah1, bp[0], bp[1]); MMAH16816(ap[1][1], ah1, bp[2], bp[3]);
                }
            }
        }

        // ---- reduce rec0, store h0_t ----
        __syncthreads();
        if (t < TT) {
            {
                char* wp = smem + PRING + wblk2 + l * 64;
#pragma unroll
                for (int mf = 0; mf < 2; ++mf)
#pragma unroll
                    for (int nf = 0; nf < 2; ++nf) {
                        const uint32_t j = (uint32_t)(mf * 2 + nf);
                        *(float4*)(wp + (((j ^ wlsw) & 3) * 16)) = *(float4*)ar[mf][nf];
                    }
            }
            __syncthreads();
            float sr[4] = {0.f, 0.f, 0.f, 0.f};
#pragma unroll
            for (int k = 0; k < 4; ++k) {
                const float4 u = *(const float4*)(smem + PRING + rquad + (uint32_t)k * 2048 + rslot);
                sr[0] += u.x; sr[1] += u.y; sr[2] += u.z; sr[3] += u.w;
            }
            const long long R0 = erow, R1 = erow + 8;
            float v0 = fmaxf(sr[0] + p0.x, 0.0f);
            float v1 = fmaxf(sr[1] + p0.y, 0.0f);
            float v2 = fmaxf(sr[2] + p1.x, 0.0f);
            float v3 = fmaxf(sr[3] + p1.y, 0.0f);
            __half2 ha = __floats2half2_rn(v0, v1);
            __half2 hb = __floats2half2_rn(v2, v3);
            __stcg((uint32_t*)(h0seq + (R0 * TT + t) * HH + ecol), *(uint32_t*)&ha);
            __stcg((uint32_t*)(h0seq + (R1 * TT + t) * HH + ecol), *(uint32_t*)&hb);
            __syncthreads();
        }

        // ---- reduce pre1 into registers (spre) ----
        float spre[4] = {0.f, 0.f, 0.f, 0.f};
        if (t >= 1) {
            {
                char* wp = smem + PRING + wblk2 + l * 64;
#pragma unroll
                for (int mf = 0; mf < 2; ++mf)
#pragma unroll
                    for (int nf = 0; nf < 2; ++nf) {
                        const uint32_t j = (uint32_t)(mf * 2 + nf);
                        *(float4*)(wp + (((j ^ wlsw) & 3) * 16)) = *(float4*)ap[mf][nf];
                    }
            }
            __syncthreads();
#pragma unroll
            for (int k = 0; k < 4; ++k) {
                const float4 u = *(const float4*)(smem + PRING + rquad + (uint32_t)k * 2048 + rslot);
                spre[0] += u.x; spre[1] += u.y; spre[2] += u.z; spre[3] += u.w;
            }
            __syncthreads();
        }

        // ---- Phase B: layer1 step u = t-1 ----
        if (t >= 1) {
            const int uu = t - 1;
            float a1[2][2][4];
#pragma unroll
            for (int i = 0; i < 2; i++)
#pragma unroll
                for (int j = 0; j < 2; j++)
#pragma unroll
                    for (int k = 0; k < 4; k++) a1[i][j][k] = 0.0f;

            if (uu >= 1) {
                const long long ab1 = (long long)((uu - 1) & 1) * BB * HH +
                                      (long long)(m0 + srr) * HH + scc * 8;
                {
                    const uint32_t d = sb + PRING;
                    CP16(d + st0,        h1pp + ab1);
                    CP16(d + 8192 + st0, h1pp + ab1 + 64);
                    CP_COMMIT();
                }
                for (int cix = 0; cix < 8; ++cix) {
                    CP_WAIT(0);
                    __syncthreads();
                    if (cix + 1 < 8) {
                        const uint32_t d = sb + PRING + (uint32_t)((cix + 1) & 1) * PSTG;
                        CP16(d + st0,        h1pp + ab1 + (cix + 1) * 128);
                        CP16(d + 8192 + st0, h1pp + ab1 + (cix + 1) * 128 + 64);
                        CP_COMMIT();
                    }
                    const uint32_t stg = sb + PRING + (uint32_t)(cix & 1) * PSTG;
#pragma unroll
                    for (int subi = 0; subi < 2; ++subi) {
                        const uint32_t ahbuf = stg + (uint32_t)subi * 8192;
                        const uint32_t wblk = (uint32_t)(2 * cix + subi) * 4096;
                        uint32_t ah0[4], ah1[4], bw[4];
                        LDMX4(ah0, ahbuf + a0base + ao);
                        LDMX4(ah1, ahbuf + a0base + 2048 + ao);
                        LDMX4(bw, sb + PW2 + wblk + b0base + bo);
                        MMAH16816(a1[0][0], ah0, bw[0], bw[1]); MMAH16816(a1[0][1], ah0, bw[2], bw[3]);
                        MMAH16816(a1[1][0], ah1, bw[0], bw[1]); MMAH16816(a1[1][1], ah1, bw[2], bw[3]);
                    }
                }
            }
            __syncthreads();
            {
                char* wp = smem + PRING + wblk2 + l * 64;
#pragma unroll
                for (int mf = 0; mf < 2; ++mf)
#pragma unroll
                    for (int nf = 0; nf < 2; ++nf) {
                        const uint32_t j = (uint32_t)(mf * 2 + nf);
                        *(float4*)(wp + (((j ^ wlsw) & 3) * 16)) = *(float4*)a1[mf][nf];
                    }
            }
            __syncthreads();
            float s1[4] = {0.f, 0.f, 0.f, 0.f};
#pragma unroll
            for (int k = 0; k < 4; ++k) {
                const float4 u = *(const float4*)(smem + PRING + rquad + (uint32_t)k * 2048 + rslot);
                s1[0] += u.x; s1[1] += u.y; s1[2] += u.z; s1[3] += u.w;
            }
            const long long R0 = erow, R1 = erow + 8;
            float v0 = fmaxf(s1[0] + spre[0] + b1v.x, 0.0f);
            float v1 = fmaxf(s1[1] + spre[1] + b1v.y, 0.0f);
            float v2 = fmaxf(s1[2] + spre[2] + b1v.x, 0.0f);
            float v3 = fmaxf(s1[3] + spre[3] + b1v.y, 0.0f);
            __half2 ha = __floats2half2_rn(v0, v1);
            __half2 hb = __floats2half2_rn(v2, v3);
            const long long ob0 = (long long)(uu & 1) * BB * HH + R0 * HH + ecol;
            const long long ob1 = (long long)(uu & 1) * BB * HH + R1 * HH + ecol;
            __stcg((uint32_t*)(h1pp + ob0), *(uint32_t*)&ha);
            __stcg((uint32_t*)(h1pp + ob1), *(uint32_t*)&hb);
            if (uu == TT - 1) {
                __stcg((float2*)(hfin + R0 * HH + ecol), make_float2(v0, v1));
                __stcg((float2*)(hfin + R1 * HH + ecol), make_float2(v2, v3));
            }
        }

        if (t < TT) grid_bar_g(grp);
    }
}

// ---------------- small scalar GEMM for fc ----------------
template <int BM, int BN, int TM, int TN>
__global__ void __launch_bounds__((BM / TM) * (BN / TN))
gemm_nt(const float* __restrict__ A, long long a_stride,
        const float* __restrict__ W, const float* __restrict__ bias,
        float* __restrict__ C, long long c_stride, int K) {
    constexpr int BK = 16, TX = BN / TN, TY = BM / TM, NT = TX * TY;
    __shared__ __align__(16) float As[BK][BM];
    __shared__ __align__(16) float Ws[BK][BN];
    const int tid = threadIdx.x, tx = tid % TX, ty = tid / TX;
    const long long m0 = (long long)blockIdx.x * BM;
    const int n0 = blockIdx.y * BN;
    float acc[TM][TN];
#pragma unroll
    for (int i = 0; i < TM; i++)
#pragma unroll
        for (int j = 0; j < TN; j++) acc[i][j] = 0.0f;
    for (int kt = 0; kt < K; kt += BK) {
#pragma unroll
        for (int idx = tid; idx < BM * 4; idx += NT) {
            const int row = idx >> 2, kq = (idx & 3) * 4;
            const float4 v = *(const float4*)(A + (m0 + row) * a_stride + kt + kq);
            As[kq][row] = v.x; As[kq + 1][row] = v.y; As[kq + 2][row] = v.z; As[kq + 3][row] = v.w;
        }
#pragma unroll
        for (int idx = tid; idx < BN * 4; idx += NT) {
            const int row = idx >> 2, kq = (idx & 3) * 4;
            const float4 v = *(const float4*)(W + (long long)(n0 + row) * K + kt + kq);
            Ws[kq][row] = v.x; Ws[kq + 1][row] = v.y; Ws[kq + 2][row] = v.z; Ws[kq + 3][row] = v.w;
        }
        __syncthreads();
#pragma unroll
        for (int kk = 0; kk < BK; kk++) {
            float a[TM], b[TN];
#pragma unroll
            for (int i = 0; i < TM; i += 4) {
                const float4 v = *(const float4*)&As[kk][ty * TM + i];
                a[i] = v.x; a[i + 1] = v.y; a[i + 2] = v.z; a[i + 3] = v.w;
            }
#pragma unroll
            for (int j = 0; j < TN; j += 4) {
                const float4 v = *(const float4*)&Ws[kk][tx * TN + j];
                b[j] = v.x; b[j + 1] = v.y; b[j + 2] = v.z; b[j + 3] = v.w;
            }
#pragma unroll
            for (int i = 0; i < TM; i++)
#pragma unroll
                for (int j = 0; j < TN; j++) acc[i][j] = fmaf(a[i], b[j], acc[i][j]);
        }
        __syncthreads();
    }
#pragma unroll
    for (int i = 0; i < TM; i++) {
        const long long m = m0 + ty * TM + i;
#pragma unroll
        for (int j = 0; j < TN; j++)
            C[m * c_stride + n0 + tx * TN + j] = acc[i][j] + bias[n0 + tx * TN + j];
    }
}

// ---------------- launch ----------------
extern "C" void kernel_launch(void* const* d_in, const int* in_sizes, int n_in,
                              void* d_out, int out_size) {
    const float* x     = (const float*)d_in[0];
    const float* W_ih0 = (const float*)d_in[1];
    const float* W_hh0 = (const float*)d_in[2];
    const float* b_ih0 = (const float*)d_in[3];
    const float* b_hh0 = (const float*)d_in[4];
    const float* W_ih1 = (const float*)d_in[5];
    const float* W_hh1 = (const float*)d_in[6];
    const float* b_ih1 = (const float*)d_in[7];
    const float* b_hh1 = (const float*)d_in[8];
    const float* fc_w  = (const float*)d_in[9];
    const float* fc_b  = (const float*)d_in[10];
    float* out = (float*)d_out;

    float *p_pre, *p_b0, *p_b1, *p_h2f;
    __half *p_xf, *p_h1f, *p_h2f16;
    __half *p_wih0, *p_wih1, *p_whh0, *p_whh1;
    cudaGetSymbolAddress((void**)&p_pre, g_pre);
    cudaGetSymbolAddress((void**)&p_b0, g_bias0);
    cudaGetSymbolAddress((void**)&p_b1, g_bias1);
    cudaGetSymbolAddress((void**)&p_h2f, g_h2f);
    cudaGetSymbolAddress((void**)&p_xf, g_xf);
    cudaGetSymbolAddress((void**)&p_h1f, g_h1f);
    cudaGetSymbolAddress((void**)&p_h2f16, g_h2f16);
    cudaGetSymbolAddress((void**)&p_wih0, g_wih0);
    cudaGetSymbolAddress((void**)&p_wih1, g_wih1);
    cudaGetSymbolAddress((void**)&p_whh0, g_whh0);
    cudaGetSymbolAddress((void**)&p_whh1, g_whh1);

    cudaFuncSetAttribute(gemm_mma, cudaFuncAttributeMaxDynamicSharedMemorySize, PG_SMEM);
    cudaFuncSetAttribute(rnn_pipe, cudaFuncAttributeMaxDynamicSharedMemorySize, PN_SMEM);

    const long long nx4 = (long long)BB * TT * II / 4;
    const long long nw04 = (long long)HH * II / 4;
    const long long nw4 = (long long)HH * HH / 4;

    // prep
    to_f16v<<<(unsigned)((nx4 + 255) / 256), 256>>>((const float4*)x, (uint2*)p_xf, nx4);
    to_f16v<<<(unsigned)((nw04 + 255) / 256), 256>>>((const float4*)W_ih0, (uint2*)p_wih0, nw04);
    bias_combine<<<(HH + 255) / 256, 256>>>(b_ih0, b_hh0, p_b0, HH);
    to_f16v<<<(unsigned)((nw4 + 255) / 256), 256>>>((const float4*)W_hh0, (uint2*)p_whh0, nw4);
    to_f16v<<<(unsigned)((nw4 + 255) / 256), 256>>>((const float4*)W_ih1, (uint2*)p_wih1, nw4);
    bias_combine<<<(HH + 255) / 256, 256>>>(b_ih1, b_hh1, p_b1, HH);
    to_f16v<<<(unsigned)((nw4 + 255) / 256), 256>>>((const float4*)W_hh1, (uint2*)p_whh1, nw4);
    // pre0 = x @ W_ih0^T + bias0
    gemm_mma<<<dim3((BB * TT) / 128, HH / 128), 256, PG_SMEM>>>(
        p_xf, p_wih0, p_b0, p_pre, II);
    // pipelined both-layer recurrence (fused pre1)
    rnn_pipe<<<128, 512, PN_SMEM>>>(p_pre, p_h1f, p_h2f16, p_h2f, p_b1);
    // fc
    gemm_nt<32, 64, 4, 4><<<dim3(BB / 32, OO / 64), 128>>>(
        p_h2f, HH, fc_w, fc_b, out, OO, HH);
}

// round 16
// speedup vs baseline: 1.4678x; 1.0218x over previous
#include <cuda_runtime.h>
#include <cuda_fp16.h>
#include <cstdint>

// ---------------- problem dims ----------------
#define BB 256
#define TT 512
#define II 512
#define HH 1024
#define OO 256

// ---------------- static device scratch (allocation-free) ----------------
__device__ __align__(16) float g_pre[BB * TT * HH];          // pre0
__device__ __align__(16) __half g_xf[BB * TT * II];
__device__ __align__(16) __half g_h1f[BB * TT * HH];         // layer0 hidden seq fp16
__device__ __align__(16) __half g_h2f16[2 * BB * HH];        // layer1 ping-pong fp16
__device__ __align__(16) float g_h2f[BB * HH];               // layer1 final fp32
__device__ __align__(16) __half g_wih0[HH * II];
__device__ __align__(16) __half g_wih1[HH * HH];
__device__ __align__(16) __half g_whh0[HH * HH];
__device__ __align__(16) __half g_whh1[HH * HH];
__device__ __align__(16) float g_bias0[HH];
__device__ __align__(16) float g_bias1[HH];
__device__ unsigned g_cnt2[256];
__device__ unsigned g_gen2[256];

// ---------------- PTX helpers (baseline PTX only) ----------------
__device__ __forceinline__ uint32_t smem_u32(const void* p) {
    uint32_t a;
    asm("{ .reg .u64 t; cvta.to.shared.u64 t, %1; cvt.u32.u64 %0, t; }" : "=r"(a) : "l"(p));
    return a;
}
#define CP16(dst, src) \
    asm volatile("cp.async.cg.shared.global [%0], [%1], 16;" :: "r"(dst), "l"(src) : "memory")
#define CP_COMMIT() asm volatile("cp.async.commit_group;" ::: "memory")
#define CP_WAIT(n)  asm volatile("cp.async.wait_group %0;" :: "n"(n) : "memory")

#define LDMX4(r, addr) \
    asm volatile("ldmatrix.sync.aligned.m8n8.x4.shared.b16 {%0,%1,%2,%3}, [%4];" \
                 : "=r"((r)[0]), "=r"((r)[1]), "=r"((r)[2]), "=r"((r)[3]) : "r"(addr))

#define MMAH16816(d, a, b0, b1) \
    asm volatile("mma.sync.aligned.m16n8k16.row.col.f32.f16.f16.f32 " \
                 "{%0,%1,%2,%3},{%4,%5,%6,%7},{%8,%9},{%0,%1,%2,%3};" \
                 : "+f"((d)[0]), "+f"((d)[1]), "+f"((d)[2]), "+f"((d)[3]) \
                 : "r"((a)[0]), "r"((a)[1]), "r"((a)[2]), "r"((a)[3]), "r"(b0), "r"(b1))

// ---------------- group grid barrier (32 CTAs per group) ----------------
__device__ __forceinline__ void grid_bar_g(int g) {
    __threadfence();
    __syncthreads();
    if (threadIdx.x == 0) {
        volatile unsigned* gen = (volatile unsigned*)&g_gen2[g * 32];
        unsigned my = *gen;
        if (atomicAdd(&g_cnt2[g * 32], 1u) == 31u) {
            atomicExch(&g_cnt2[g * 32], 0u);
            __threadfence();
            *gen = my + 1;
        } else {
            while (*gen == my) { }
        }
    }
    __syncthreads();
}

// ---------------- prep kernels ----------------
__global__ void to_f16v(const float4* __restrict__ s, uint2* __restrict__ o, long long n4) {
    long long i = (long long)blockIdx.x * blockDim.x + threadIdx.x;
    if (i < n4) {
        float4 v = s[i];
        __half2 a = __floats2half2_rn(v.x, v.y);
        __half2 b = __floats2half2_rn(v.z, v.w);
        uint2 r;
        r.x = *(uint32_t*)&a; r.y = *(uint32_t*)&b;
        o[i] = r;
    }
}
__global__ void bias_combine(const float* __restrict__ a, const float* __restrict__ b,
                             float* __restrict__ out, int n) {
    int i = blockIdx.x * blockDim.x + threadIdx.x;
    if (i < n) out[i] = a[i] + b[i];
}

// ================= fp16 HMMA pre-activation GEMM (pre0 only) =================
#define PG_STAGE 32768
#define PG_SMEM  (3 * PG_STAGE)

__global__ void __launch_bounds__(256, 1)
gemm_mma(const __half* __restrict__ Af, const __half* __restrict__ Wf,
         const float* __restrict__ bias, float* __restrict__ C, int K) {
    extern __shared__ __align__(128) char smem[];
    const uint32_t sb = smem_u32(smem);
    const int tid = threadIdx.x, l = tid & 31, w = tid >> 5;
    const long long m0 = (long long)blockIdx.x * 128;
    const int n0 = blockIdx.y * 128;
    const int nch = K >> 6;

    const int r0 = tid >> 3, c = tid & 7;
    const uint32_t sd0 = (uint32_t)r0 * 128 + (((uint32_t)c * 16) ^ (((uint32_t)r0 & 7) * 16));

    const int m_off = (w & 3) * 32, n_off = (w >> 2) * 64;
    const int arw = m_off + (l & 7) + ((l & 8) ? 8 : 0);
    const uint32_t abase = (uint32_t)arw * 128;
    const uint32_t ax = ((uint32_t)arw & 7) * 16;
    const uint32_t akb = (l & 16) ? 16 : 0;
    const int brw = n_off + (l & 7) + ((l & 16) ? 8 : 0);
    const uint32_t bbase = (uint32_t)brw * 128;
    const uint32_t bx = ((uint32_t)brw & 7) * 16;
    const uint32_t bkb = (l & 8) ? 16 : 0;

    float acc[2][8][4];
#pragma unroll
    for (int i = 0; i < 2; i++)
#pragma unroll
        for (int j = 0; j < 8; j++)
#pragma unroll
            for (int k = 0; k < 4; k++) acc[i][j][k] = 0.0f;

    auto issue = [&](int kc) {
        const uint32_t d = sb + (uint32_t)(kc % 3) * PG_STAGE;
        const int ko = kc * 64 + c * 8;
#pragma unroll
        for (int j = 0; j < 4; ++j) {
            const long long ar = (m0 + r0 + 32 * j) * (long long)K + ko;
            const long long wr = ((long long)(n0 + r0 + 32 * j)) * K + ko;
            const uint32_t du = d + sd0 + j * 4096;
            CP16(du,          Af + ar);
            CP16(du + 16384,  Wf + wr);
        }
        CP_COMMIT();
    };

    issue(0);
    issue(1);

    for (int kc = 0; kc < nch; ++kc) {
        if (kc < nch - 1) CP_WAIT(1); else CP_WAIT(0);
        __syncthreads();
        if (kc + 2 < nch) issue(kc + 2);

        const uint32_t st = sb + (uint32_t)(kc % 3) * PG_STAGE;
#pragma unroll
        for (int ks = 0; ks < 4; ++ks) {
            uint32_t ah0[4], ah1[4];
            const uint32_t ao = ((uint32_t)(ks * 32) + akb) ^ ax;
            LDMX4(ah0, st + abase + ao);
            LDMX4(ah1, st + abase + 2048 + ao);
            uint32_t bh[4][4];
            const uint32_t bo = ((uint32_t)(ks * 32) + bkb) ^ bx;
#pragma unroll
            for (int nb = 0; nb < 4; ++nb)
                LDMX4(bh[nb], st + 16384 + bbase + nb * 2048 + bo);
#pragma unroll
            for (int nb = 0; nb < 4; ++nb) {
                MMAH16816(acc[0][2 * nb],     ah0, bh[nb][0], bh[nb][1]);
                MMAH16816(acc[0][2 * nb + 1], ah0, bh[nb][2], bh[nb][3]);
                MMAH16816(acc[1][2 * nb],     ah1, bh[nb][0], bh[nb][1]);
                MMAH16816(acc[1][2 * nb + 1], ah1, bh[nb][2], bh[nb][3]);
            }
        }
        __syncthreads();
    }

#pragma unroll
    for (int mf = 0; mf < 2; ++mf) {
        const long long R0 = m0 + m_off + mf * 16 + (l >> 2);
#pragma unroll
        for (int nf = 0; nf < 8; ++nf) {
            const int col = n0 + n_off + nf * 8 + (l & 3) * 2;
            const float2 bv = __ldg((const float2*)(bias + col));
            float2 o0, o1;
            o0.x = acc[mf][nf][0] + bv.x; o0.y = acc[mf][nf][1] + bv.y;
            o1.x = acc[mf][nf][2] + bv.x; o1.y = acc[mf][nf][3] + bv.y;
            __stcg((float2*)(C + R0 * HH + col), o0);
            __stcg((float2*)(C + (R0 + 8) * HH + col), o1);
        }
    }
}

// ================= PIPELINED both-layer recurrence (merged reduce) =================
// 128 CTAs (4 grp x 32 ntile), 512 thr, 1 CTA/SM.
// Resident: W_hh0@0, W_ih1@64K, W_hh1@128K. Ring @192K: 2 x 16KB; reduce overlaps.
// Tick t: Phase A = rec0 step t + pre1_{t-1} (ap kept in regs);
// Phase B = rec1 step t-1; ap merged into rec1 partials before the single reduce.
#define PW1 65536
#define PW2 131072
#define PRING 196608
#define PSTG 16384
#define PN_SMEM (PRING + 32768)   // 224KB

__global__ void __launch_bounds__(512, 1)
rnn_pipe(const float* __restrict__ pre0,
         __half* __restrict__ h0seq,
         __half* __restrict__ h1pp,
         float* __restrict__ hfin,
         const float* __restrict__ bias1) {
    extern __shared__ __align__(128) char smem[];
    const uint32_t sb = smem_u32(smem);
    const int tid = threadIdx.x, l = tid & 31, w = tid >> 5;
    const int grp = blockIdx.x & 3;
    const int m0 = grp * 64;
    const int n0 = (blockIdx.x >> 2) * 32;

    for (int u = tid; u < 4096; u += 512) {
        const int blk = u >> 8, rem = u & 255, r = rem >> 3, cc = rem & 7;
        const uint32_t dst = (uint32_t)blk * 4096 + (uint32_t)r * 128 +
                             (((uint32_t)cc * 16) ^ (((uint32_t)r & 7) * 16));
        const long long src = (long long)(n0 + r) * HH + blk * 64 + cc * 8;
        *(uint4*)(smem + dst)       = *(const uint4*)(g_whh0 + src);
        *(uint4*)(smem + PW1 + dst) = *(const uint4*)(g_wih1 + src);
        *(uint4*)(smem + PW2 + dst) = *(const uint4*)(g_whh1 + src);
    }
    __syncthreads();

    const int srr = tid >> 3, scc = tid & 7;
    const uint32_t st0 = (uint32_t)srr * 128 + (((uint32_t)scc * 16) ^ (((uint32_t)srr & 7) * 16));

    const int mpos = w & 1, npos = (w >> 1) & 1, kslot = w >> 2;
    const uint32_t ax = ((uint32_t)l & 7) * 16;
    const uint32_t akb = (l & 16) ? 16u : 0u;
    const uint32_t a0base = (uint32_t)(mpos * 32 + (l & 15)) * 128;
    const uint32_t bkb = (l & 8) ? 16u : 0u;
    const uint32_t b0base = (uint32_t)(npos * 16 + (l & 7) + ((l & 16) ? 8 : 0)) * 128;
    const uint32_t kob = (uint32_t)(kslot * 32);
    const uint32_t ao = (kob + akb) ^ ax;
    const uint32_t bo = (kob + bkb) ^ ax;
    const uint32_t wblk2 = (uint32_t)((mpos * 2 + npos) * 4 + kslot) * 2048;
    const uint32_t wlsw = ((uint32_t)l & 3) ^ (((uint32_t)l >> 2) & 3);

    const int rmp = tid >> 8, rnp = (tid >> 7) & 1, rl = (tid >> 2) & 31, q = tid & 3;
    const int erow = m0 + rmp * 32 + (q >> 1) * 16 + (rl >> 2);
    const int ecol = n0 + rnp * 16 + (q & 1) * 8 + (rl & 3) * 2;
    const uint32_t rquad = (uint32_t)((rmp * 2 + rnp) * 4) * 2048 + (uint32_t)rl * 64;
    const uint32_t rslot = (((uint32_t)q ^ ((uint32_t)rl & 3) ^ (((uint32_t)rl >> 2) & 3)) & 3) * 16;
    const float2 b1v = __ldg((const float2*)(bias1 + ecol));

    for (int t = 0; t <= TT; ++t) {
        float2 p0, p1;
        if (t < TT) {
            p0 = __ldcg((const float2*)(pre0 + ((long long)erow * TT + t) * HH + ecol));
            p1 = __ldcg((const float2*)(pre0 + ((long long)(erow + 8) * TT + t) * HH + ecol));
        }

        float ar[2][2][4], ap[2][2][4];
#pragma unroll
        for (int i = 0; i < 2; i++)
#pragma unroll
            for (int j = 0; j < 2; j++)
#pragma unroll
                for (int k = 0; k < 4; k++) { ar[i][j][k] = 0.0f; ap[i][j][k] = 0.0f; }

        // ---- Phase A: layer0 step t (rec0 + pre1; ap stays in regs) ----
        if (t >= 1) {
            const long long ab = ((long long)(m0 + srr) * TT + (t - 1)) * HH + scc * 8;
            {
                const uint32_t d = sb + PRING;
                CP16(d + st0,        h0seq + ab);
                CP16(d + 8192 + st0, h0seq + ab + 64);
                CP_COMMIT();
            }
            for (int cix = 0; cix < 8; ++cix) {
                CP_WAIT(0);
                __syncthreads();
                if (cix + 1 < 8) {
                    const uint32_t d = sb + PRING + (uint32_t)((cix + 1) & 1) * PSTG;
                    CP16(d + st0,        h0seq + ab + (cix + 1) * 128);
                    CP16(d + 8192 + st0, h0seq + ab + (cix + 1) * 128 + 64);
                    CP_COMMIT();
                }
                const uint32_t stg = sb + PRING + (uint32_t)(cix & 1) * PSTG;
#pragma unroll
                for (int subi = 0; subi < 2; ++subi) {
                    const uint32_t ahbuf = stg + (uint32_t)subi * 8192;
                    const uint32_t wblk = (uint32_t)(2 * cix + subi) * 4096;
                    uint32_t ah0[4], ah1[4], br[4], bp[4];
                    LDMX4(ah0, ahbuf + a0base + ao);
                    LDMX4(ah1, ahbuf + a0base + 2048 + ao);
                    LDMX4(br, sb + wblk + b0base + bo);
                    LDMX4(bp, sb + PW1 + wblk + b0base + bo);
                    MMAH16816(ar[0][0], ah0, br[0], br[1]); MMAH16816(ar[0][1], ah0, br[2], br[3]);
                    MMAH16816(ar[1][0], ah1, br[0], br[1]); MMAH16816(ar[1][1], ah1, br[2], br[3]);
                    MMAH16816(ap[0][0], ah0, bp[0], bp[1]); MMAH16816(ap[0][1], ah0, bp[2], bp[3]);
                    MMAH16816(ap[1][0], ah1, bp[0], bp[1]); MMAH16816(ap[1][1], ah1, bp[2], bp[3]);
                }
            }
        }

        // ---- reduce rec0, store h0_t ----
        __syncthreads();
        if (t < TT) {
            {
                char* wp = smem + PRING + wblk2 + l * 64;
#pragma unroll
                for (int mf = 0; mf < 2; ++mf)
#pragma unroll
                    for (int nf = 0; nf < 2; ++nf) {
                        const uint32_t j = (uint32_t)(mf * 2 + nf);
                        *(float4*)(wp + (((j ^ wlsw) & 3) * 16)) = *(float4*)ar[mf][nf];
                    }
            }
            __syncthreads();
            float sr[4] = {0.f, 0.f, 0.f, 0.f};
#pragma unroll
            for (int k = 0; k < 4; ++k) {
                const float4 u = *(const float4*)(smem + PRING + rquad + (uint32_t)k * 2048 + rslot);
                sr[0] += u.x; sr[1] += u.y; sr[2] += u.z; sr[3] += u.w;
            }
            const long long R0 = erow, R1 = erow + 8;
            float v0 = fmaxf(sr[0] + p0.x, 0.0f);
            float v1 = fmaxf(sr[1] + p0.y, 0.0f);
            float v2 = fmaxf(sr[2] + p1.x, 0.0f);
            float v3 = fmaxf(sr[3] + p1.y, 0.0f);
            __half2 ha = __floats2half2_rn(v0, v1);
            __half2 hb = __floats2half2_rn(v2, v3);
            __stcg((uint32_t*)(h0seq + (R0 * TT + t) * HH + ecol), *(uint32_t*)&ha);
            __stcg((uint32_t*)(h0seq + (R1 * TT + t) * HH + ecol), *(uint32_t*)&hb);
            __syncthreads();   // reduce region free before Phase B staging
        }

        // ---- Phase B: layer1 step u = t-1 (ap merged into partials) ----
        if (t >= 1) {
            const int uu = t - 1;
            float a1[2][2][4];
#pragma unroll
            for (int i = 0; i < 2; i++)
#pragma unroll
                for (int j = 0; j < 2; j++)
#pragma unroll
                    for (int k = 0; k < 4; k++) a1[i][j][k] = 0.0f;

            if (uu >= 1) {
                const long long ab1 = (long long)((uu - 1) & 1) * BB * HH +
                                      (long long)(m0 + srr) * HH + scc * 8;
                {
                    const uint32_t d = sb + PRING;
                    CP16(d + st0,        h1pp + ab1);
                    CP16(d + 8192 + st0, h1pp + ab1 + 64);
                    CP_COMMIT();
                }
                for (int cix = 0; cix < 8; ++cix) {
                    CP_WAIT(0);
                    __syncthreads();
                    if (cix + 1 < 8) {
                        const uint32_t d = sb + PRING + (uint32_t)((cix + 1) & 1) * PSTG;
                        CP16(d + st0,        h1pp + ab1 + (cix + 1) * 128);
                        CP16(d + 8192 + st0, h1pp + ab1 + (cix + 1) * 128 + 64);
                        CP_COMMIT();
                    }
                    const uint32_t stg = sb + PRING + (uint32_t)(cix & 1) * PSTG;
#pragma unroll
                    for (int subi = 0; subi < 2; ++subi) {
                        const uint32_t ahbuf = stg + (uint32_t)subi * 8192;
                        const uint32_t wblk = (uint32_t)(2 * cix + subi) * 4096;
                        uint32_t ah0[4], ah1[4], bw[4];
                        LDMX4(ah0, ahbuf + a0base + ao);
                        LDMX4(ah1, ahbuf + a0base + 2048 + ao);
                        LDMX4(bw, sb + PW2 + wblk + b0base + bo);
                        MMAH16816(a1[0][0], ah0, bw[0], bw[1]); MMAH16816(a1[0][1], ah0, bw[2], bw[3]);
                        MMAH16816(a1[1][0], ah1, bw[0], bw[1]); MMAH16816(a1[1][1], ah1, bw[2], bw[3]);
                    }
                }
            }
            // merge pre1 partials into rec1 partials (register adds, no reduce round)
#pragma unroll
            for (int i = 0; i < 2; i++)
#pragma unroll
                for (int j = 0; j < 2; j++)
#pragma unroll
                    for (int k = 0; k < 4; k++) a1[i][j][k] += ap[i][j][k];

            __syncthreads();
            {
                char* wp = smem + PRING + wblk2 + l * 64;
#pragma unroll
                for (int mf = 0; mf < 2; ++mf)
#pragma unroll
                    for (int nf = 0; nf < 2; ++nf) {
                        const uint32_t j = (uint32_t)(mf * 2 + nf);
                        *(float4*)(wp + (((j ^ wlsw) & 3) * 16)) = *(float4*)a1[mf][nf];
                    }
            }
            __syncthreads();
            float s1[4] = {0.f, 0.f, 0.f, 0.f};
#pragma unroll
            for (int k = 0; k < 4; ++k) {
                const float4 u = *(const float4*)(smem + PRING + rquad + (uint32_t)k * 2048 + rslot);
                s1[0] += u.x; s1[1] += u.y; s1[2] += u.z; s1[3] += u.w;
            }
            const long long R0 = erow, R1 = erow + 8;
            float v0 = fmaxf(s1[0] + b1v.x, 0.0f);
            float v1 = fmaxf(s1[1] + b1v.y, 0.0f);
            float v2 = fmaxf(s1[2] + b1v.x, 0.0f);
            float v3 = fmaxf(s1[3] + b1v.y, 0.0f);
            __half2 ha = __floats2half2_rn(v0, v1);
            __half2 hb = __floats2half2_rn(v2, v3);
            const long long ob0 = (long long)(uu & 1) * BB * HH + R0 * HH + ecol;
            const long long ob1 = (long long)(uu & 1) * BB * HH + R1 * HH + ecol;
            __stcg((uint32_t*)(h1pp + ob0), *(uint32_t*)&ha);
            __stcg((uint32_t*)(h1pp + ob1), *(uint32_t*)&hb);
            if (uu == TT - 1) {
                __stcg((float2*)(hfin + R0 * HH + ecol), make_float2(v0, v1));
                __stcg((float2*)(hfin + R1 * HH + ecol), make_float2(v2, v3));
            }
        }

        if (t < TT) grid_bar_g(grp);
    }
}

// ---------------- small scalar GEMM for fc ----------------
template <int BM, int BN, int TM, int TN>
__global__ void __launch_bounds__((BM / TM) * (BN / TN))
gemm_nt(const float* __restrict__ A, long long a_stride,
        const float* __restrict__ W, const float* __restrict__ bias,
        float* __restrict__ C, long long c_stride, int K) {
    constexpr int BK = 16, TX = BN / TN, TY = BM / TM, NT = TX * TY;
    __shared__ __align__(16) float As[BK][BM];
    __shared__ __align__(16) float Ws[BK][BN];
    const int tid = threadIdx.x, tx = tid % TX, ty = tid / TX;
    const long long m0 = (long long)blockIdx.x * BM;
    const int n0 = blockIdx.y * BN;
    float acc[TM][TN];
#pragma unroll
    for (int i = 0; i < TM; i++)
#pragma unroll
        for (int j = 0; j < TN; j++) acc[i][j] = 0.0f;
    for (int kt = 0; kt < K; kt += BK) {
#pragma unroll
        for (int idx = tid; idx < BM * 4; idx += NT) {
            const int row = idx >> 2, kq = (idx & 3) * 4;
            const float4 v = *(const float4*)(A + (m0 + row) * a_stride + kt + kq);
            As[kq][row] = v.x; As[kq + 1][row] = v.y; As[kq + 2][row] = v.z; As[kq + 3][row] = v.w;
        }
#pragma unroll
        for (int idx = tid; idx < BN * 4; idx += NT) {
            const int row = idx >> 2, kq = (idx & 3) * 4;
            const float4 v = *(const float4*)(W + (long long)(n0 + row) * K + kt + kq);
            Ws[kq][row] = v.x; Ws[kq + 1][row] = v.y; Ws[kq + 2][row] = v.z; Ws[kq + 3][row] = v.w;
        }
        __syncthreads();
#pragma unroll
        for (int kk = 0; kk < BK; kk++) {
            float a[TM], b[TN];
#pragma unroll
            for (int i = 0; i < TM; i += 4) {
                const float4 v = *(const float4*)&As[kk][ty * TM + i];
                a[i] = v.x; a[i + 1] = v.y; a[i + 2] = v.z; a[i + 3] = v.w;
            }
#pragma unroll
            for (int j = 0; j < TN; j += 4) {
                const float4 v = *(const float4*)&Ws[kk][tx * TN + j];
                b[j] = v.x; b[j + 1] = v.y; b[j + 2] = v.z; b[j + 3] = v.w;
            }
#pragma unroll
            for (int i = 0; i < TM; i++)
#pragma unroll
                for (int j = 0; j < TN; j++) acc[i][j] = fmaf(a[i], b[j], acc[i][j]);
        }
        __syncthreads();
    }
#pragma unroll
    for (int i = 0; i < TM; i++) {
        const long long m = m0 + ty * TM + i;
#pragma unroll
        for (int j = 0; j < TN; j++)
            C[m * c_stride + n0 + tx * TN + j] = acc[i][j] + bias[n0 + tx * TN + j];
    }
}

// ---------------- launch ----------------
extern "C" void kernel_launch(void* const* d_in, const int* in_sizes, int n_in,
                              void* d_out, int out_size) {
    const float* x     = (const float*)d_in[0];
    const float* W_ih0 = (const float*)d_in[1];
    const float* W_hh0 = (const float*)d_in[2];
    const float* b_ih0 = (const float*)d_in[3];
    const float* b_hh0 = (const float*)d_in[4];
    const float* W_ih1 = (const float*)d_in[5];
    const float* W_hh1 = (const float*)d_in[6];
    const float* b_ih1 = (const float*)d_in[7];
    const float* b_hh1 = (const float*)d_in[8];
    const float* fc_w  = (const float*)d_in[9];
    const float* fc_b  = (const float*)d_in[10];
    float* out = (float*)d_out;

    float *p_pre, *p_b0, *p_b1, *p_h2f;
    __half *p_xf, *p_h1f, *p_h2f16;
    __half *p_wih0, *p_wih1, *p_whh0, *p_whh1;
    cudaGetSymbolAddress((void**)&p_pre, g_pre);
    cudaGetSymbolAddress((void**)&p_b0, g_bias0);
    cudaGetSymbolAddress((void**)&p_b1, g_bias1);
    cudaGetSymbolAddress((void**)&p_h2f, g_h2f);
    cudaGetSymbolAddress((void**)&p_xf, g_xf);
    cudaGetSymbolAddress((void**)&p_h1f, g_h1f);
    cudaGetSymbolAddress((void**)&p_h2f16, g_h2f16);
    cudaGetSymbolAddress((void**)&p_wih0, g_wih0);
    cudaGetSymbolAddress((void**)&p_wih1, g_wih1);
    cudaGetSymbolAddress((void**)&p_whh0, g_whh0);
    cudaGetSymbolAddress((void**)&p_whh1, g_whh1);

    cudaFuncSetAttribute(gemm_mma, cudaFuncAttributeMaxDynamicSharedMemorySize, PG_SMEM);
    cudaFuncSetAttribute(rnn_pipe, cudaFuncAttributeMaxDynamicSharedMemorySize, PN_SMEM);

    const long long nx4 = (long long)BB * TT * II / 4;
    const long long nw04 = (long long)HH * II / 4;
    const long long nw4 = (long long)HH * HH / 4;

    // prep
    to_f16v<<<(unsigned)((nx4 + 255) / 256), 256>>>((const float4*)x, (uint2*)p_xf, nx4);
    to_f16v<<<(unsigned)((nw04 + 255) / 256), 256>>>((const float4*)W_ih0, (uint2*)p_wih0, nw04);
    bias_combine<<<(HH + 255) / 256, 256>>>(b_ih0, b_hh0, p_b0, HH);
    to_f16v<<<(unsigned)((nw4 + 255) / 256), 256>>>((const float4*)W_hh0, (uint2*)p_whh0, nw4);
    to_f16v<<<(unsigned)((nw4 + 255) / 256), 256>>>((const float4*)W_ih1, (uint2*)p_wih1, nw4);
    bias_combine<<<(HH + 255) / 256, 256>>>(b_ih1, b_hh1, p_b1, HH);
    to_f16v<<<(unsigned)((nw4 + 255) / 256), 256>>>((const float4*)W_hh1, (uint2*)p_whh1, nw4);
    // pre0 = x @ W_ih0^T + bias0
    gemm_mma<<<dim3((BB * TT) / 128, HH / 128), 256, PG_SMEM>>>(
        p_xf, p_wih0, p_b0, p_pre, II);
    // pipelined both-layer recurrence (fused pre1, merged reduce)
    rnn_pipe<<<128, 512, PN_SMEM>>>(p_pre, p_h1f, p_h2f16, p_h2f, p_b1);
    // fc
    gemm_nt<32, 64, 4, 4><<<dim3(BB / 32, OO / 64), 128>>>(
        p_h2f, HH, fc_w, fc_b, out, OO, HH);
}

// round 17
// speedup vs baseline: 1.4715x; 1.0025x over previous
#include <cuda_runtime.h>
#include <cuda_fp16.h>
#include <cstdint>

// ---------------- problem dims ----------------
#define BB 256
#define TT 512
#define II 512
#define HH 1024
#define OO 256

// ---------------- static device scratch (allocation-free) ----------------
__device__ __align__(16) float g_pre[BB * TT * HH];          // pre0
__device__ __align__(16) __half g_xf[BB * TT * II];
__device__ __align__(16) __half g_h1f[BB * TT * HH];         // layer0 hidden seq fp16
__device__ __align__(16) __half g_h2f16[2 * BB * HH];        // layer1 ping-pong fp16
__device__ __align__(16) float g_h2f[BB * HH];               // layer1 final fp32
__device__ __align__(16) __half g_wih0[HH * II];
__device__ __align__(16) __half g_wih1[HH * HH];
__device__ __align__(16) __half g_whh0[HH * HH];
__device__ __align__(16) __half g_whh1[HH * HH];
__device__ __align__(16) float g_bias0[HH];
__device__ __align__(16) float g_bias1[HH];
__device__ unsigned g_cnt2[256];
__device__ unsigned g_gen2[256];

// ---------------- PTX helpers (baseline PTX only) ----------------
__device__ __forceinline__ uint32_t smem_u32(const void* p) {
    uint32_t a;
    asm("{ .reg .u64 t; cvta.to.shared.u64 t, %1; cvt.u32.u64 %0, t; }" : "=r"(a) : "l"(p));
    return a;
}
#define CP16(dst, src) \
    asm volatile("cp.async.cg.shared.global [%0], [%1], 16;" :: "r"(dst), "l"(src) : "memory")
#define CP_COMMIT() asm volatile("cp.async.commit_group;" ::: "memory")
#define CP_WAIT(n)  asm volatile("cp.async.wait_group %0;" :: "n"(n) : "memory")

#define LDMX4(r, addr) \
    asm volatile("ldmatrix.sync.aligned.m8n8.x4.shared.b16 {%0,%1,%2,%3}, [%4];" \
                 : "=r"((r)[0]), "=r"((r)[1]), "=r"((r)[2]), "=r"((r)[3]) : "r"(addr))

#define MMAH16816(d, a, b0, b1) \
    asm volatile("mma.sync.aligned.m16n8k16.row.col.f32.f16.f16.f32 " \
                 "{%0,%1,%2,%3},{%4,%5,%6,%7},{%8,%9},{%0,%1,%2,%3};" \
                 : "+f"((d)[0]), "+f"((d)[1]), "+f"((d)[2]), "+f"((d)[3]) \
                 : "r"((a)[0]), "r"((a)[1]), "r"((a)[2]), "r"((a)[3]), "r"(b0), "r"(b1))

// ---------------- group grid barrier (32 CTAs per group) ----------------
__device__ __forceinline__ void grid_bar_g(int g) {
    __threadfence();
    __syncthreads();
    if (threadIdx.x == 0) {
        volatile unsigned* gen = (volatile unsigned*)&g_gen2[g * 32];
        unsigned my = *gen;
        if (atomicAdd(&g_cnt2[g * 32], 1u) == 31u) {
            atomicExch(&g_cnt2[g * 32], 0u);
            __threadfence();
            *gen = my + 1;
        } else {
            while (*gen == my) { }
        }
    }
    __syncthreads();
}

// ---------------- prep kernels ----------------
__global__ void to_f16v(const float4* __restrict__ s, uint2* __restrict__ o, long long n4) {
    long long i = (long long)blockIdx.x * blockDim.x + threadIdx.x;
    if (i < n4) {
        float4 v = s[i];
        __half2 a = __floats2half2_rn(v.x, v.y);
        __half2 b = __floats2half2_rn(v.z, v.w);
        uint2 r;
        r.x = *(uint32_t*)&a; r.y = *(uint32_t*)&b;
        o[i] = r;
    }
}
__global__ void bias_combine(const float* __restrict__ a, const float* __restrict__ b,
                             float* __restrict__ out, int n) {
    int i = blockIdx.x * blockDim.x + threadIdx.x;
    if (i < n) out[i] = a[i] + b[i];
}

// ================= fp16 HMMA pre-activation GEMM (pre0 only) =================
#define PG_STAGE 32768
#define PG_SMEM  (3 * PG_STAGE)

__global__ void __launch_bounds__(256, 1)
gemm_mma(const __half* __restrict__ Af, const __half* __restrict__ Wf,
         const float* __restrict__ bias, float* __restrict__ C, int K) {
    extern __shared__ __align__(128) char smem[];
    const uint32_t sb = smem_u32(smem);
    const int tid = threadIdx.x, l = tid & 31, w = tid >> 5;
    const long long m0 = (long long)blockIdx.x * 128;
    const int n0 = blockIdx.y * 128;
    const int nch = K >> 6;

    const int r0 = tid >> 3, c = tid & 7;
    const uint32_t sd0 = (uint32_t)r0 * 128 + (((uint32_t)c * 16) ^ (((uint32_t)r0 & 7) * 16));

    const int m_off = (w & 3) * 32, n_off = (w >> 2) * 64;
    const int arw = m_off + (l & 7) + ((l & 8) ? 8 : 0);
    const uint32_t abase = (uint32_t)arw * 128;
    const uint32_t ax = ((uint32_t)arw & 7) * 16;
    const uint32_t akb = (l & 16) ? 16 : 0;
    const int brw = n_off + (l & 7) + ((l & 16) ? 8 : 0);
    const uint32_t bbase = (uint32_t)brw * 128;
    const uint32_t bx = ((uint32_t)brw & 7) * 16;
    const uint32_t bkb = (l & 8) ? 16 : 0;

    float acc[2][8][4];
#pragma unroll
    for (int i = 0; i < 2; i++)
#pragma unroll
        for (int j = 0; j < 8; j++)
#pragma unroll
            for (int k = 0; k < 4; k++) acc[i][j][k] = 0.0f;

    auto issue = [&](int kc) {
        const uint32_t d = sb + (uint32_t)(kc % 3) * PG_STAGE;
        const int ko = kc * 64 + c * 8;
#pragma unroll
        for (int j = 0; j < 4; ++j) {
            const long long ar = (m0 + r0 + 32 * j) * (long long)K + ko;
            const long long wr = ((long long)(n0 + r0 + 32 * j)) * K + ko;
            const uint32_t du = d + sd0 + j * 4096;
            CP16(du,          Af + ar);
            CP16(du + 16384,  Wf + wr);
        }
        CP_COMMIT();
    };

    issue(0);
    issue(1);

    for (int kc = 0; kc < nch; ++kc) {
        if (kc < nch - 1) CP_WAIT(1); else CP_WAIT(0);
        __syncthreads();
        if (kc + 2 < nch) issue(kc + 2);

        const uint32_t st = sb + (uint32_t)(kc % 3) * PG_STAGE;
#pragma unroll
        for (int ks = 0; ks < 4; ++ks) {
            uint32_t ah0[4], ah1[4];
            const uint32_t ao = ((uint32_t)(ks * 32) + akb) ^ ax;
            LDMX4(ah0, st + abase + ao);
            LDMX4(ah1, st + abase + 2048 + ao);
            uint32_t bh[4][4];
            const uint32_t bo = ((uint32_t)(ks * 32) + bkb) ^ bx;
#pragma unroll
            for (int nb = 0; nb < 4; ++nb)
                LDMX4(bh[nb], st + 16384 + bbase + nb * 2048 + bo);
#pragma unroll
            for (int nb = 0; nb < 4; ++nb) {
                MMAH16816(acc[0][2 * nb],     ah0, bh[nb][0], bh[nb][1]);
                MMAH16816(acc[0][2 * nb + 1], ah0, bh[nb][2], bh[nb][3]);
                MMAH16816(acc[1][2 * nb],     ah1, bh[nb][0], bh[nb][1]);
                MMAH16816(acc[1][2 * nb + 1], ah1, bh[nb][2], bh[nb][3]);
            }
        }
        __syncthreads();
    }

#pragma unroll
    for (int mf = 0; mf < 2; ++mf) {
        const long long R0 = m0 + m_off + mf * 16 + (l >> 2);
#pragma unroll
        for (int nf = 0; nf < 8; ++nf) {
            const int col = n0 + n_off + nf * 8 + (l & 3) * 2;
            const float2 bv = __ldg((const float2*)(bias + col));
            float2 o0, o1;
            o0.x = acc[mf][nf][0] + bv.x; o0.y = acc[mf][nf][1] + bv.y;
            o1.x = acc[mf][nf][2] + bv.x; o1.y = acc[mf][nf][3] + bv.y;
            __stcg((float2*)(C + R0 * HH + col), o0);
            __stcg((float2*)(C + (R0 + 8) * HH + col), o1);
        }
    }
}

// ================= PIPELINED both-layer recurrence (merged reduce) =================
// 128 CTAs (4 grp x 32 ntile), 512 thr, 1 CTA/SM.
// Resident: W_hh0@0, W_ih1@64K, W_hh1@128K. Ring @192K: 2 x 16KB; reduce overlaps.
// Tick t: Phase A = rec0 step t + pre1_{t-1} (ap kept in regs);
// Phase B = rec1 step t-1; ap merged into rec1 partials before the single reduce.
#define PW1 65536
#define PW2 131072
#define PRING 196608
#define PSTG 16384
#define PN_SMEM (PRING + 32768)   // 224KB

__global__ void __launch_bounds__(512, 1)
rnn_pipe(const float* __restrict__ pre0,
         __half* __restrict__ h0seq,
         __half* __restrict__ h1pp,
         float* __restrict__ hfin,
         const float* __restrict__ bias1) {
    extern __shared__ __align__(128) char smem[];
    const uint32_t sb = smem_u32(smem);
    const int tid = threadIdx.x, l = tid & 31, w = tid >> 5;
    const int grp = blockIdx.x & 3;
    const int m0 = grp * 64;
    const int n0 = (blockIdx.x >> 2) * 32;

    for (int u = tid; u < 4096; u += 512) {
        const int blk = u >> 8, rem = u & 255, r = rem >> 3, cc = rem & 7;
        const uint32_t dst = (uint32_t)blk * 4096 + (uint32_t)r * 128 +
                             (((uint32_t)cc * 16) ^ (((uint32_t)r & 7) * 16));
        const long long src = (long long)(n0 + r) * HH + blk * 64 + cc * 8;
        *(uint4*)(smem + dst)       = *(const uint4*)(g_whh0 + src);
        *(uint4*)(smem + PW1 + dst) = *(const uint4*)(g_wih1 + src);
        *(uint4*)(smem + PW2 + dst) = *(const uint4*)(g_whh1 + src);
    }
    __syncthreads();

    const int srr = tid >> 3, scc = tid & 7;
    const uint32_t st0 = (uint32_t)srr * 128 + (((uint32_t)scc * 16) ^ (((uint32_t)srr & 7) * 16));

    const int mpos = w & 1, npos = (w >> 1) & 1, kslot = w >> 2;
    const uint32_t ax = ((uint32_t)l & 7) * 16;
    const uint32_t akb = (l & 16) ? 16u : 0u;
    const uint32_t a0base = (uint32_t)(mpos * 32 + (l & 15)) * 128;
    const uint32_t bkb = (l & 8) ? 16u : 0u;
    const uint32_t b0base = (uint32_t)(npos * 16 + (l & 7) + ((l & 16) ? 8 : 0)) * 128;
    const uint32_t kob = (uint32_t)(kslot * 32);
    const uint32_t ao = (kob + akb) ^ ax;
    const uint32_t bo = (kob + bkb) ^ ax;
    const uint32_t wblk2 = (uint32_t)((mpos * 2 + npos) * 4 + kslot) * 2048;
    const uint32_t wlsw = ((uint32_t)l & 3) ^ (((uint32_t)l >> 2) & 3);

    const int rmp = tid >> 8, rnp = (tid >> 7) & 1, rl = (tid >> 2) & 31, q = tid & 3;
    const int erow = m0 + rmp * 32 + (q >> 1) * 16 + (rl >> 2);
    const int ecol = n0 + rnp * 16 + (q & 1) * 8 + (rl & 3) * 2;
    const uint32_t rquad = (uint32_t)((rmp * 2 + rnp) * 4) * 2048 + (uint32_t)rl * 64;
    const uint32_t rslot = (((uint32_t)q ^ ((uint32_t)rl & 3) ^ (((uint32_t)rl >> 2) & 3)) & 3) * 16;
    const float2 b1v = __ldg((const float2*)(bias1 + ecol));

    for (int t = 0; t <= TT; ++t) {
        float2 p0, p1;
        if (t < TT) {
            p0 = __ldcg((const float2*)(pre0 + ((long long)erow * TT + t) * HH + ecol));
            p1 = __ldcg((const float2*)(pre0 + ((long long)(erow + 8) * TT + t) * HH + ecol));
        }

        float ar[2][2][4], ap[2][2][4];
#pragma unroll
        for (int i = 0; i < 2; i++)
#pragma unroll
            for (int j = 0; j < 2; j++)
#pragma unroll
                for (int k = 0; k < 4; k++) { ar[i][j][k] = 0.0f; ap[i][j][k] = 0.0f; }

        // ---- Phase A: layer0 step t (rec0 + pre1; ap stays in regs) ----
        if (t >= 1) {
            const long long ab = ((long long)(m0 + srr) * TT + (t - 1)) * HH + scc * 8;
            {
                const uint32_t d = sb + PRING;
                CP16(d + st0,        h0seq + ab);
                CP16(d + 8192 + st0, h0seq + ab + 64);
                CP_COMMIT();
            }
            for (int cix = 0; cix < 8; ++cix) {
                CP_WAIT(0);
                __syncthreads();
                if (cix + 1 < 8) {
                    const uint32_t d = sb + PRING + (uint32_t)((cix + 1) & 1) * PSTG;
                    CP16(d + st0,        h0seq + ab + (cix + 1) * 128);
                    CP16(d + 8192 + st0, h0seq + ab + (cix + 1) * 128 + 64);
                    CP_COMMIT();
                }
                const uint32_t stg = sb + PRING + (uint32_t)(cix & 1) * PSTG;
#pragma unroll
                for (int subi = 0; subi < 2; ++subi) {
                    const uint32_t ahbuf = stg + (uint32_t)subi * 8192;
                    const uint32_t wblk = (uint32_t)(2 * cix + subi) * 4096;
                    uint32_t ah0[4], ah1[4], br[4], bp[4];
                    LDMX4(ah0, ahbuf + a0base + ao);
                    LDMX4(ah1, ahbuf + a0base + 2048 + ao);
                    LDMX4(br, sb + wblk + b0base + bo);
                    LDMX4(bp, sb + PW1 + wblk + b0base + bo);
                    MMAH16816(ar[0][0], ah0, br[0], br[1]); MMAH16816(ar[0][1], ah0, br[2], br[3]);
                    MMAH16816(ar[1][0], ah1, br[0], br[1]); MMAH16816(ar[1][1], ah1, br[2], br[3]);
                    MMAH16816(ap[0][0], ah0, bp[0], bp[1]); MMAH16816(ap[0][1], ah0, bp[2], bp[3]);
                    MMAH16816(ap[1][0], ah1, bp[0], bp[1]); MMAH16816(ap[1][1], ah1, bp[2], bp[3]);
                }
            }
        }

        // ---- reduce rec0, store h0_t ----
        __syncthreads();
        if (t < TT) {
            {
                char* wp = smem + PRING + wblk2 + l * 64;
#pragma unroll
                for (int mf = 0; mf < 2; ++mf)
#pragma unroll
                    for (int nf = 0; nf < 2; ++nf) {
                        const uint32_t j = (uint32_t)(mf * 2 + nf);
                        *(float4*)(wp + (((j ^ wlsw) & 3) * 16)) = *(float4*)ar[mf][nf];
                    }
            }
            __syncthreads();
            float sr[4] = {0.f, 0.f, 0.f, 0.f};
#pragma unroll
            for (int k = 0; k < 4; ++k) {
                const float4 u = *(const float4*)(smem + PRING + rquad + (uint32_t)k * 2048 + rslot);
                sr[0] += u.x; sr[1] += u.y; sr[2] += u.z; sr[3] += u.w;
            }
            const long long R0 = erow, R1 = erow + 8;
            float v0 = fmaxf(sr[0] + p0.x, 0.0f);
            float v1 = fmaxf(sr[1] + p0.y, 0.0f);
            float v2 = fmaxf(sr[2] + p1.x, 0.0f);
            float v3 = fmaxf(sr[3] + p1.y, 0.0f);
            __half2 ha = __floats2half2_rn(v0, v1);
            __half2 hb = __floats2half2_rn(v2, v3);
            __stcg((uint32_t*)(h0seq + (R0 * TT + t) * HH + ecol), *(uint32_t*)&ha);
            __stcg((uint32_t*)(h0seq + (R1 * TT + t) * HH + ecol), *(uint32_t*)&hb);
            __syncthreads();   // reduce region free before Phase B staging
        }

        // ---- Phase B: layer1 step u = t-1 (ap merged into partials) ----
        if (t >= 1) {
            const int uu = t - 1;
            float a1[2][2][4];
#pragma unroll
            for (int i = 0; i < 2; i++)
#pragma unroll
                for (int j = 0; j < 2; j++)
#pragma unroll
                    for (int k = 0; k < 4; k++) a1[i][j][k] = 0.0f;

            if (uu >= 1) {
                const long long ab1 = (long long)((uu - 1) & 1) * BB * HH +
                                      (long long)(m0 + srr) * HH + scc * 8;
                {
                    const uint32_t d = sb + PRING;
                    CP16(d + st0,        h1pp + ab1);
                    CP16(d + 8192 + st0, h1pp + ab1 + 64);
                    CP_COMMIT();
                }
                for (int cix = 0; cix < 8; ++cix) {
                    CP_WAIT(0);
                    __syncthreads();
                    if (cix + 1 < 8) {
                        const uint32_t d = sb + PRING + (uint32_t)((cix + 1) & 1) * PSTG;
                        CP16(d + st0,        h1pp + ab1 + (cix + 1) * 128);
                        CP16(d + 8192 + st0, h1pp + ab1 + (cix + 1) * 128 + 64);
                        CP_COMMIT();
                    }
                    const uint32_t stg = sb + PRING + (uint32_t)(cix & 1) * PSTG;
#pragma unroll
                    for (int subi = 0; subi < 2; ++subi) {
                        const uint32_t ahbuf = stg + (uint32_t)subi * 8192;
                        const uint32_t wblk = (uint32_t)(2 * cix + subi) * 4096;
                        uint32_t ah0[4], ah1[4], bw[4];
                        LDMX4(ah0, ahbuf + a0base + ao);
                        LDMX4(ah1, ahbuf + a0base + 2048 + ao);
                        LDMX4(bw, sb + PW2 + wblk + b0base + bo);
                        MMAH16816(a1[0][0], ah0, bw[0], bw[1]); MMAH16816(a1[0][1], ah0, bw[2], bw[3]);
                        MMAH16816(a1[1][0], ah1, bw[0], bw[1]); MMAH16816(a1[1][1], ah1, bw[2], bw[3]);
                    }
                }
            }
            // merge pre1 partials into rec1 partials (register adds, no reduce round)
#pragma unroll
            for (int i = 0; i < 2; i++)
#pragma unroll
                for (int j = 0; j < 2; j++)
#pragma unroll
                    for (int k = 0; k < 4; k++) a1[i][j][k] += ap[i][j][k];

            __syncthreads();
            {
                char* wp = smem + PRING + wblk2 + l * 64;
#pragma unroll
                for (int mf = 0; mf < 2; ++mf)
#pragma unroll
                    for (int nf = 0; nf < 2; ++nf) {
                        const uint32_t j = (uint32_t)(mf * 2 + nf);
                        *(float4*)(wp + (((j ^ wlsw) & 3) * 16)) = *(float4*)a1[mf][nf];
                    }
            }
            __syncthreads();
            float s1[4] = {0.f, 0.f, 0.f, 0.f};
#pragma unroll
            for (int k = 0; k < 4; ++k) {
                const float4 u = *(const float4*)(smem + PRING + rquad + (uint32_t)k * 2048 + rslot);
                s1[0] += u.x; s1[1] += u.y; s1[2] += u.z; s1[3] += u.w;
            }
            const long long R0 = erow, R1 = erow + 8;
            float v0 = fmaxf(s1[0] + b1v.x, 0.0f);
            float v1 = fmaxf(s1[1] + b1v.y, 0.0f);
            float v2 = fmaxf(s1[2] + b1v.x, 0.0f);
            float v3 = fmaxf(s1[3] + b1v.y, 0.0f);
            __half2 ha = __floats2half2_rn(v0, v1);
            __half2 hb = __floats2half2_rn(v2, v3);
            const long long ob0 = (long long)(uu & 1) * BB * HH + R0 * HH + ecol;
            const long long ob1 = (long long)(uu & 1) * BB * HH + R1 * HH + ecol;
            __stcg((uint32_t*)(h1pp + ob0), *(uint32_t*)&ha);
            __stcg((uint32_t*)(h1pp + ob1), *(uint32_t*)&hb);
            if (uu == TT - 1) {
                __stcg((float2*)(hfin + R0 * HH + ecol), make_float2(v0, v1));
                __stcg((float2*)(hfin + R1 * HH + ecol), make_float2(v2, v3));
            }
        }

        if (t < TT) grid_bar_g(grp);
    }
}

// ---------------- small scalar GEMM for fc ----------------
template <int BM, int BN, int TM, int TN>
__global__ void __launch_bounds__((BM / TM) * (BN / TN))
gemm_nt(const float* __restrict__ A, long long a_stride,
        const float* __restrict__ W, const float* __restrict__ bias,
        float* __restrict__ C, long long c_stride, int K) {
    constexpr int BK = 16, TX = BN / TN, TY = BM / TM, NT = TX * TY;
    __shared__ __align__(16) float As[BK][BM];
    __shared__ __align__(16) float Ws[BK][BN];
    const int tid = threadIdx.x, tx = tid % TX, ty = tid / TX;
    const long long m0 = (long long)blockIdx.x * BM;
    const int n0 = blockIdx.y * BN;
    float acc[TM][TN];
#pragma unroll
    for (int i = 0; i < TM; i++)
#pragma unroll
        for (int j = 0; j < TN; j++) acc[i][j] = 0.0f;
    for (int kt = 0; kt < K; kt += BK) {
#pragma unroll
        for (int idx = tid; idx < BM * 4; idx += NT) {
            const int row = idx >> 2, kq = (idx & 3) * 4;
            const float4 v = *(const float4*)(A + (m0 + row) * a_stride + kt + kq);
            As[kq][row] = v.x; As[kq + 1][row] = v.y; As[kq + 2][row] = v.z; As[kq + 3][row] = v.w;
        }
#pragma unroll
        for (int idx = tid; idx < BN * 4; idx += NT) {
            const int row = idx >> 2, kq = (idx & 3) * 4;
            const float4 v = *(const float4*)(W + (long long)(n0 + row) * K + kt + kq);
            Ws[kq][row] = v.x; Ws[kq + 1][row] = v.y; Ws[kq + 2][row] = v.z; Ws[kq + 3][row] = v.w;
        }
        __syncthreads();
#pragma unroll
        for (int kk = 0; kk < BK; kk++) {
            float a[TM], b[TN];
#pragma unroll
            for (int i = 0; i < TM; i += 4) {
                const float4 v = *(const float4*)&As[kk][ty * TM + i];
                a[i] = v.x; a[i + 1] = v.y; a[i + 2] = v.z; a[i + 3] = v.w;
            }
#pragma unroll
            for (int j = 0; j < TN; j += 4) {
                const float4 v = *(const float4*)&Ws[kk][tx * TN + j];
                b[j] = v.x; b[j + 1] = v.y; b[j + 2] = v.z; b[j + 3] = v.w;
            }
#pragma unroll
            for (int i = 0; i < TM; i++)
#pragma unroll
                for (int j = 0; j < TN; j++) acc[i][j] = fmaf(a[i], b[j], acc[i][j]);
        }
        __syncthreads();
    }
#pragma unroll
    for (int i = 0; i < TM; i++) {
        const long long m = m0 + ty * TM + i;
#pragma unroll
        for (int j = 0; j < TN; j++)
            C[m * c_stride + n0 + tx * TN + j] = acc[i][j] + bias[n0 + tx * TN + j];
    }
}

// ---------------- launch ----------------
extern "C" void kernel_launch(void* const* d_in, const int* in_sizes, int n_in,
                              void* d_out, int out_size) {
    const float* x     = (const float*)d_in[0];
    const float* W_ih0 = (const float*)d_in[1];
    const float* W_hh0 = (const float*)d_in[2];
    const float* b_ih0 = (const float*)d_in[3];
    const float* b_hh0 = (const float*)d_in[4];
    const float* W_ih1 = (const float*)d_in[5];
    const float* W_hh1 = (const float*)d_in[6];
    const float* b_ih1 = (const float*)d_in[7];
    const float* b_hh1 = (const float*)d_in[8];
    const float* fc_w  = (const float*)d_in[9];
    const float* fc_b  = (const float*)d_in[10];
    float* out = (float*)d_out;

    float *p_pre, *p_b0, *p_b1, *p_h2f;
    __half *p_xf, *p_h1f, *p_h2f16;
    __half *p_wih0, *p_wih1, *p_whh0, *p_whh1;
    cudaGetSymbolAddress((void**)&p_pre, g_pre);
    cudaGetSymbolAddress((void**)&p_b0, g_bias0);
    cudaGetSymbolAddress((void**)&p_b1, g_bias1);
    cudaGetSymbolAddress((void**)&p_h2f, g_h2f);
    cudaGetSymbolAddress((void**)&p_xf, g_xf);
    cudaGetSymbolAddress((void**)&p_h1f, g_h1f);
    cudaGetSymbolAddress((void**)&p_h2f16, g_h2f16);
    cudaGetSymbolAddress((void**)&p_wih0, g_wih0);
    cudaGetSymbolAddress((void**)&p_wih1, g_wih1);
    cudaGetSymbolAddress((void**)&p_whh0, g_whh0);
    cudaGetSymbolAddress((void**)&p_whh1, g_whh1);

    cudaFuncSetAttribute(gemm_mma, cudaFuncAttributeMaxDynamicSharedMemorySize, PG_SMEM);
    cudaFuncSetAttribute(rnn_pipe, cudaFuncAttributeMaxDynamicSharedMemorySize, PN_SMEM);

    const long long nx4 = (long long)BB * TT * II / 4;
    const long long nw04 = (long long)HH * II / 4;
    const long long nw4 = (long long)HH * HH / 4;

    // prep
    to_f16v<<<(unsigned)((nx4 + 255) / 256), 256>>>((const float4*)x, (uint2*)p_xf, nx4);
    to_f16v<<<(unsigned)((nw04 + 255) / 256), 256>>>((const float4*)W_ih0, (uint2*)p_wih0, nw04);
    bias_combine<<<(HH + 255) / 256, 256>>>(b_ih0, b_hh0, p_b0, HH);
    to_f16v<<<(unsigned)((nw4 + 255) / 256), 256>>>((const float4*)W_hh0, (uint2*)p_whh0, nw4);
    to_f16v<<<(unsigned)((nw4 + 255) / 256), 256>>>((const float4*)W_ih1, (uint2*)p_wih1, nw4);
    bias_combine<<<(HH + 255) / 256, 256>>>(b_ih1, b_hh1, p_b1, HH);
    to_f16v<<<(unsigned)((nw4 + 255) / 256), 256>>>((const float4*)W_hh1, (uint2*)p_whh1, nw4);
    // pre0 = x @ W_ih0^T + bias0
    gemm_mma<<<dim3((BB * TT) / 128, HH / 128), 256, PG_SMEM>>>(
        p_xf, p_wih0, p_b0, p_pre, II);
    // pipelined both-layer recurrence (fused pre1, merged reduce)
    rnn_pipe<<<128, 512, PN_SMEM>>>(p_pre, p_h1f, p_h2f16, p_h2f, p_b1);
    // fc
    gemm_nt<32, 64, 4, 4><<<dim3(BB / 32, OO / 64), 128>>>(
        p_h2f, HH, fc_w, fc_b, out, OO, HH);
}